// round 12
// baseline (speedup 1.0000x reference)
#include <cuda_runtime.h>
#include <math.h>

#define T_ 1024
#define L_ 32
#define D_ 512
#define P_ 512
#define H_ 2048
#define NB 128
#define NT 1024
#define NTH (NB * NT)   // 131072
#define SCALE_ 0.044194173824159216f  // 1/sqrt(512)
#define LN_EPS 1e-5f
#define SMEM_BYTES 70656

// output layout offsets (floats)
#define OFF_ALIGNED 0
#define OFF_AP      16384
#define OFF_TW      16793600
#define OFF_FA      16794624

// ---------------- scratch (device globals) ----------------
__device__ __align__(16) float g_rawq[L_ * P_];     // new_prompt @ Wq (no bias)
__device__ __align__(16) float g_u[D_];             // Wk @ task_vec
__device__ __align__(16) float g_v[D_];             // Wk @ pooled_q
__device__ __align__(16) float g_c01[2];            // c0 = bk·tv, c1 = bk·pq
__device__ __align__(16) float g_dotu[T_];
__device__ __align__(16) float g_dotv[T_];
__device__ __align__(16) float g_wcp[4 * L_ * D_];  // wc partials (4-way t)
__device__ __align__(16) float g_wc[L_ * D_];       // weighted conditioned
__device__ __align__(16) float g_wkr[L_ * P_];      // wc @ Wk (raw)
__device__ __align__(16) float g_wvr[L_ * P_];      // wc @ Wv (raw)
__device__ __align__(16) float g_oacc[L_ * D_];     // (ep+bv) @ Wo
__device__ __align__(16) float g_evolved[L_ * D_];
__device__ __align__(16) float g_h1[L_ * H_];       // evolved @ Wa1 (raw)
__device__ __align__(16) float g_mlpp[4 * L_ * D_]; // mlp partials (4-way k)

// grid barrier state
__device__ unsigned g_cnt;
__device__ unsigned g_gen;

// ---------------- grid barrier: single-thread fence (CG-style) ----------------
__device__ __forceinline__ void gbar() {
    __syncthreads();
    if (threadIdx.x == 0) {
        asm volatile("fence.acq_rel.gpu;" ::: "memory");   // release block's writes
        unsigned gen = *(volatile unsigned*)&g_gen;
        if (atomicAdd(&g_cnt, 1u) == (unsigned)(NB - 1)) {
            g_cnt = 0u;
            asm volatile("fence.acq_rel.gpu;" ::: "memory");
            *(volatile unsigned*)&g_gen = gen + 1u;
        } else {
            while (*(volatile unsigned*)&g_gen == gen) __nanosleep(32);
            asm volatile("fence.acq_rel.gpu;" ::: "memory"); // acquire
        }
    }
    __syncthreads();
}

// ---------------- reductions ----------------
__device__ __forceinline__ float warp_sum(float v) {
#pragma unroll
    for (int o = 16; o > 0; o >>= 1) v += __shfl_xor_sync(0xffffffffu, v, o);
    return v;
}
__device__ __forceinline__ float warp_max(float v) {
#pragma unroll
    for (int o = 16; o > 0; o >>= 1) v = fmaxf(v, __shfl_xor_sync(0xffffffffu, v, o));
    return v;
}
// block reductions for NT=1024 (32 warps)
__device__ __forceinline__ float blk_sum(float v, float* red) {
    int w = threadIdx.x >> 5, lane = threadIdx.x & 31;
    v = warp_sum(v);
    if (lane == 0) red[w] = v;
    __syncthreads();
    if (w == 0) {
        float r = red[lane];
        r = warp_sum(r);
        if (lane == 0) red[0] = r;
    }
    __syncthreads();
    float out = red[0];
    __syncthreads();
    return out;
}
__device__ __forceinline__ float blk_max(float v, float* red) {
    int w = threadIdx.x >> 5, lane = threadIdx.x & 31;
    v = warp_max(v);
    if (lane == 0) red[w] = v;
    __syncthreads();
    if (w == 0) {
        float r = red[lane];
        r = warp_max(r);
        if (lane == 0) red[0] = r;
    }
    __syncthreads();
    float out = red[0];
    __syncthreads();
    return out;
}
__device__ __forceinline__ float dot4(float4 a, float4 b) {
    return fmaf(a.x, b.x, fmaf(a.y, b.y, fmaf(a.z, b.z, a.w * b.w)));
}

// ---------------- megakernel ----------------
__global__ void __launch_bounds__(NT, 1)
mega(const float* __restrict__ base, const float* __restrict__ np_,
     const float* __restrict__ te, const float* __restrict__ Wt,
     const float* __restrict__ bt, const float* __restrict__ Wq,
     const float* __restrict__ bq, const float* __restrict__ Wk,
     const float* __restrict__ bk, const float* __restrict__ Wv,
     const float* __restrict__ bv, const float* __restrict__ Wo,
     const float* __restrict__ bo, const float* __restrict__ Wa1,
     const float* __restrict__ ba1, const float* __restrict__ Wa2,
     const float* __restrict__ ba2, const float* __restrict__ gin,
     const float* __restrict__ bin, const float* __restrict__ gout,
     const float* __restrict__ bout, float* __restrict__ out) {
    extern __shared__ float sm[];

    const int bid = blockIdx.x;
    const int tid = threadIdx.x;
    const int gtid = bid * NT + tid;
    const int w = tid >> 5, lane = tid & 31;
    const float4* base4 = reinterpret_cast<const float4*>(base);

    // ======== S0: rawq direct (blk 0-15); npmean->pq->v,c1 (blk 16); tv->u,c0 (blk 17)
    if (bid < 16) {
        float* sNp = sm;   // 1024 = rows (2*bid, 2*bid+1) of np
        sNp[tid] = np_[bid * 1024 + tid];
        __syncthreads();
        int l = tid >> 9, p = tid & 511;
        const float* xr = sNp + l * 512;
        const float* wcol = Wq + p;
        float a0 = 0.f, a1 = 0.f;
#pragma unroll 8
        for (int k = 0; k < 512; k += 2) {
            a0 = fmaf(xr[k], wcol[(size_t)k * P_], a0);
            a1 = fmaf(xr[k + 1], wcol[(size_t)(k + 1) * P_], a1);
        }
        g_rawq[bid * 1024 + tid] = a0 + a1;
    } else if (bid == 16) {
        float* sNp = sm;          // 512: npmean
        float* sPQ = sm + 512;    // 512
        float* sRed = sm + 1024;  // 32
        if (tid < 512) {
            float s = 0.f;
#pragma unroll 8
            for (int l = 0; l < 32; l++) s += np_[l * 512 + tid];
            sNp[tid] = s * (1.f / 32.f);
        }
        __syncthreads();
        if (tid < 512) {
            const float* wcol = Wq + tid;
            float a0 = 0.f, a1 = 0.f;
#pragma unroll 8
            for (int k = 0; k < 512; k += 2) {
                a0 = fmaf(sNp[k], wcol[(size_t)k * P_], a0);
                a1 = fmaf(sNp[k + 1], wcol[(size_t)(k + 1) * P_], a1);
            }
            sPQ[tid] = a0 + a1 + bq[tid];
        }
        __syncthreads();
        {   // v = Wk @ pq, warp-per-row (32 warps x 16 rows)
            const float4* pq4 = reinterpret_cast<const float4*>(sPQ);
#pragma unroll 4
            for (int r = 0; r < 16; r++) {
                int d = w * 16 + r;
                const float4* row = reinterpret_cast<const float4*>(Wk + (size_t)d * P_);
                float av = 0.f;
#pragma unroll
                for (int i = 0; i < 4; i++) av += dot4(row[lane + 32 * i], pq4[lane + 32 * i]);
                av = warp_sum(av);
                if (lane == 0) g_v[d] = av;
            }
        }
        float t1 = (tid < 512) ? bk[tid] * sPQ[tid] : 0.f;
        float c1 = blk_sum(t1, sRed);
        if (tid == 0) g_c01[1] = c1;
    } else if (bid == 17) {
        float* sTe = sm;          // 512
        float* sTV = sm + 512;    // 512
        float* sRed = sm + 1024;  // 32
        if (tid < 512) sTe[tid] = te[tid];
        __syncthreads();
        if (tid < 512) {
            const float* wcol = Wt + tid;
            float a0 = 0.f, a1 = 0.f;
#pragma unroll 8
            for (int k = 0; k < 512; k += 2) {
                a0 = fmaf(sTe[k], wcol[(size_t)k * P_], a0);
                a1 = fmaf(sTe[k + 1], wcol[(size_t)(k + 1) * P_], a1);
            }
            sTV[tid] = tanhf(a0 + a1 + bt[tid]);
        }
        __syncthreads();
        {   // u = Wk @ tv, warp-per-row
            const float4* tv4 = reinterpret_cast<const float4*>(sTV);
#pragma unroll 4
            for (int r = 0; r < 16; r++) {
                int d = w * 16 + r;
                const float4* row = reinterpret_cast<const float4*>(Wk + (size_t)d * P_);
                float au = 0.f;
#pragma unroll
                for (int i = 0; i < 4; i++) au += dot4(row[lane + 32 * i], tv4[lane + 32 * i]);
                au = warp_sum(au);
                if (lane == 0) g_u[d] = au;
            }
        }
        float t0 = (tid < 512) ? bk[tid] * sTV[tid] : 0.f;
        float c0 = blk_sum(t0, sRed);
        if (tid == 0) g_c01[0] = c0;
    }
    gbar();

    // ======== S1: dots directly from base (all blocks; THE DRAM pass)
    {
        float4* sU4 = reinterpret_cast<float4*>(sm);         // 128
        float4* sV4 = reinterpret_cast<float4*>(sm) + 128;   // 128
        float* sPu = sm + 1024;  // 32
        float* sPv = sm + 1056;  // 32
        if (tid < 128) sU4[tid] = reinterpret_cast<const float4*>(g_u)[tid];
        else if (tid < 256) sV4[tid - 128] = reinterpret_cast<const float4*>(g_v)[tid - 128];
        __syncthreads();
        int t = bid * 8 + (w >> 2);
        int seg = w & 3;
        const float4* bp = base4 + (size_t)t * 4096 + seg * 1024 + lane;
        float au = 0.f, av = 0.f;
#pragma unroll 8
        for (int i = 0; i < 32; i++) {
            float4 b4 = bp[i * 32];
            float4 u4 = sU4[lane + 32 * (i & 3)];
            float4 v4 = sV4[lane + 32 * (i & 3)];
            au += dot4(b4, u4);
            av += dot4(b4, v4);
        }
        au = warp_sum(au);
        av = warp_sum(av);
        if (lane == 0) { sPu[w] = au; sPv[w] = av; }
        __syncthreads();
        if (tid < 8) {
            float su = sPu[4 * tid] + sPu[4 * tid + 1] + sPu[4 * tid + 2] + sPu[4 * tid + 3];
            g_dotu[bid * 8 + tid] = su * (1.f / 32.f);
        } else if (tid < 16) {
            int q = tid - 8;
            float sv = sPv[4 * q] + sPv[4 * q + 1] + sPv[4 * q + 2] + sPv[4 * q + 3];
            g_dotv[bid * 8 + q] = sv * (1.f / 32.f);
        }
    }
    gbar();

    // ======== S2: task softmaxes (redundant; tid==t) + wc partials (all blocks; base from L2)
    {
        float* sC = sm;                // 1024 coef
        float* sRed = sm + 1024;       // 32
        float4* sP4 = reinterpret_cast<float4*>(sm + 1056); // 1024 float4

        float c0 = g_c01[0], c1 = g_c01[1];

        float s1 = SCALE_ * (g_dotu[tid] + c0);
        float dv = g_dotv[tid];
        float m1 = blk_max(s1, sRed);
        float e1 = expf(s1 - m1);
        float tw1 = e1 / blk_sum(e1, sRed);

        float s2 = SCALE_ * ((1.f + tw1) * dv + c1);
        float m2 = blk_max(s2, sRed);
        float e2 = expf(s2 - m2);
        float ta = e2 / blk_sum(e2, sRed);

        float tw = 0.5f * (tw1 + ta);
        float S = blk_sum(tw, sRed);
        float tw2 = tw / fmaxf(S, 1e-6f);
        sC[tid] = tw2 * (1.f + tw1);
        if (bid == 0) out[OFF_TW + tid] = tw2;
        __syncthreads();

        // wc partial: block (l = bid>>2, q = bid&3); thread (c = tid&127, ts = tid>>7)
        int l = bid >> 2, q = bid & 3;
        int c = tid & 127, ts = tid >> 7;       // ts 0..7
        int t0 = q * 256 + ts * 32;
        const float4* bp = base4 + (size_t)t0 * 4096 + l * 128 + c;
        const float* cf = sC + t0;
        float4 acc = {0.f, 0.f, 0.f, 0.f};
#pragma unroll 8
        for (int i = 0; i < 32; i++) {
            float cv = cf[i];
            float4 b4 = bp[i * 4096];
            acc.x = fmaf(cv, b4.x, acc.x);
            acc.y = fmaf(cv, b4.y, acc.y);
            acc.z = fmaf(cv, b4.z, acc.z);
            acc.w = fmaf(cv, b4.w, acc.w);
        }
        sP4[ts * 128 + c] = acc;
        __syncthreads();
        if (tid < 128) {
            float4 a = sP4[tid];
#pragma unroll
            for (int g2 = 1; g2 < 8; g2++) {
                float4 b = sP4[g2 * 128 + tid];
                a.x += b.x; a.y += b.y; a.z += b.z; a.w += b.w;
            }
            reinterpret_cast<float4*>(g_wcp)[q * 4096 + l * 128 + tid] = a;
        }
    }
    gbar();

    // ======== S3: fold wc (redundant) + wkr/wvr column-strip GEMM (all blocks)
    {
        float* sX = sm;               // 32 x 513 padded
        float* sPart = sm + 16416;    // 1024
        const float* W = (bid < 64) ? Wk : Wv;
        int colbase = (bid & 63) * 8;
        for (int i = tid; i < 16384; i += NT) {
            float x = g_wcp[i] + g_wcp[16384 + i] + g_wcp[32768 + i] + g_wcp[49152 + i];
            int l = i >> 9, k = i & 511;
            sX[l * 513 + k] = x;
            if (bid == 0) g_wc[i] = x;
        }
        __syncthreads();
        int o = tid & 255;                  // l = o>>3, dd = o&7
        int l = o >> 3, dd = o & 7;
        int kq = tid >> 8;                  // 0..3
        const float* xr = sX + l * 513 + kq * 128;
        const float* wcol = W + (size_t)(kq * 128) * P_ + colbase + dd;
        float a0 = 0.f, a1 = 0.f;
#pragma unroll 8
        for (int k = 0; k < 128; k += 2) {
            a0 = fmaf(xr[k], wcol[(size_t)k * P_], a0);
            a1 = fmaf(xr[k + 1], wcol[(size_t)(k + 1) * P_], a1);
        }
        sPart[kq * 256 + o] = a0 + a1;
        __syncthreads();
        if (tid < 256) {
            float v = sPart[tid] + sPart[256 + tid] + sPart[512 + tid] + sPart[768 + tid];
            int ll = tid >> 3, d2 = tid & 7;
            if (bid < 64) g_wkr[ll * 512 + colbase + d2] = v;
            else          g_wvr[ll * 512 + colbase + d2] = v;
        }
    }
    gbar();

    // ======== S4: flog + softmax + ep + oacc (block = (l = bid>>2, dq = bid&3))
    {
        float* sF = sm;          // 32
        float* sFa = sm + 32;    // 32
        float* sE = sm + 64;     // 512
        float* sP = sm + 576;    // 1024
        int l = bid >> 2, dq = bid & 3;
        const float* qr = g_rawq + l * P_;
        {   // warp w computes flog[l][w]
            const float* kr = g_wkr + w * P_;
            float a = 0.f;
#pragma unroll
            for (int i = 0; i < 16; i++) {
                int e = lane + 32 * i;
                a = fmaf(qr[e] + bq[e], kr[e] + bk[e], a);
            }
            a = warp_sum(a);
            if (lane == 0) sF[w] = SCALE_ * a;
        }
        __syncthreads();
        if (w == 0) {
            float x = sF[lane];
            float m = warp_max(x);
            float e = expf(x - m);
            float s = warp_sum(e);
            float f = e / s;
            sFa[lane] = f;
            if (dq == 0) out[OFF_FA + l * 32 + lane] = f;
        }
        __syncthreads();
        if (tid < 512) {
            float a = bv[tid];
#pragma unroll
            for (int j = 0; j < 32; j++) a = fmaf(sFa[j], g_wvr[j * P_ + tid], a);
            sE[tid] = a;
        }
        __syncthreads();
        {
            int dd = tid & 127, ks = tid >> 7;  // ks 0..7
            int d = dq * 128 + dd;
            const float* wcol = Wo + (size_t)(ks * 64) * D_ + d;
            const float* er = sE + ks * 64;
            float a0 = 0.f, a1 = 0.f;
#pragma unroll 8
            for (int k = 0; k < 64; k += 2) {
                a0 = fmaf(er[k], wcol[(size_t)k * D_], a0);
                a1 = fmaf(er[k + 1], wcol[(size_t)(k + 1) * D_], a1);
            }
            sP[ks * 128 + dd] = a0 + a1;
        }
        __syncthreads();
        if (tid < 128) {
            float v = 0.f;
#pragma unroll
            for (int g2 = 0; g2 < 8; g2++) v += sP[g2 * 128 + tid];
            g_oacc[l * 512 + dq * 128 + tid] = v;
        }
    }
    gbar();

    // ======== S5: LN1 (redundant, warp-per-row) + h1 strip GEMM (all blocks)
    {
        float* sEvo = sm;             // 32 x 513
        float* sPart = sm + 16416;    // 1024
        {
            int row = w;
            float x[16];
            float s = 0.f;
#pragma unroll
            for (int i = 0; i < 16; i++) {
                int e = lane + 32 * i;
                x[i] = g_wc[row * 512 + e] + g_oacc[row * 512 + e] + bo[e];
                s += x[i];
            }
            float mean = warp_sum(s) * (1.f / D_);
            float v = 0.f;
#pragma unroll
            for (int i = 0; i < 16; i++) { float d = x[i] - mean; v = fmaf(d, d, v); }
            float inv = rsqrtf(warp_sum(v) * (1.f / D_) + LN_EPS);
#pragma unroll
            for (int i = 0; i < 16; i++) {
                int e = lane + 32 * i;
                float y = (x[i] - mean) * inv * gin[e] + bin[e];
                sEvo[row * 513 + e] = y;
                if (bid == 0) g_evolved[row * 512 + e] = y;
            }
        }
        __syncthreads();
        {   // warp: dd = w&15 (col in strip), kh = w>>4; lane = row
            int dd = w & 15, kh = w >> 4;
            int p = bid * 16 + dd;
            const float* xr = sEvo + lane * 513 + kh * 256;
            const float* wcol = Wa1 + (size_t)(kh * 256) * H_ + p;
            float a0 = 0.f, a1 = 0.f;
#pragma unroll 8
            for (int k = 0; k < 256; k += 2) {
                a0 = fmaf(xr[k], wcol[(size_t)k * H_], a0);
                a1 = fmaf(xr[k + 1], wcol[(size_t)(k + 1) * H_], a1);
            }
            sPart[kh * 512 + lane * 16 + dd] = a0 + a1;
        }
        __syncthreads();
        if (tid < 512) {
            int l = tid >> 4, dd = tid & 15;
            g_h1[l * H_ + bid * 16 + dd] = sPart[tid] + sPart[512 + tid];
        }
    }
    gbar();

    // ======== S6: mlp strip GEMM (block = (ks = bid&3, dseg = bid>>2))
    {
        float* sH = sm;               // 32 x 513
        float* sPart = sm + 16416;    // 1024
        int ks = bid & 3, dseg = bid >> 2;
        for (int i = tid; i < 16384; i += NT) {
            int row = i >> 9, k = i & 511;
            int kg = ks * 512 + k;
            sH[row * 513 + k] = fmaxf(g_h1[row * H_ + kg] + ba1[kg], 0.f);
        }
        __syncthreads();
        {
            int dd = w & 15, kh = w >> 4;
            int d = dseg * 16 + dd;
            const float* hr = sH + lane * 513 + kh * 256;
            const float* wcol = Wa2 + (size_t)(ks * 512 + kh * 256) * D_ + d;
            float a0 = 0.f, a1 = 0.f;
#pragma unroll 8
            for (int k = 0; k < 256; k += 2) {
                a0 = fmaf(hr[k], wcol[(size_t)k * D_], a0);
                a1 = fmaf(hr[k + 1], wcol[(size_t)(k + 1) * D_], a1);
            }
            sPart[kh * 512 + lane * 16 + dd] = a0 + a1;
        }
        __syncthreads();
        if (tid < 512) {
            int l = tid >> 4, dd = tid & 15;
            g_mlpp[ks * 16384 + l * 512 + dseg * 16 + dd] = sPart[tid] + sPart[512 + tid];
        }
    }
    gbar();

    // ======== S7: LN2 (redundant, warp-per-row) + broadcast (all blocks)
    {
        float* sAl = sm;   // 16384
        {
            int row = w;
            float x[16];
            float s = 0.f;
#pragma unroll
            for (int i = 0; i < 16; i++) {
                int e = lane + 32 * i;
                int o = row * 512 + e;
                x[i] = g_evolved[o] + g_mlpp[o] + g_mlpp[16384 + o] +
                       g_mlpp[32768 + o] + g_mlpp[49152 + o] + ba2[e];
                s += x[i];
            }
            float mean = warp_sum(s) * (1.f / D_);
            float v = 0.f;
#pragma unroll
            for (int i = 0; i < 16; i++) { float d = x[i] - mean; v = fmaf(d, d, v); }
            float inv = rsqrtf(warp_sum(v) * (1.f / D_) + LN_EPS);
#pragma unroll
            for (int i = 0; i < 16; i++) {
                int e = lane + 32 * i;
                float y = (x[i] - mean) * inv * gout[e] + bout[e];
                sAl[row * 512 + e] = y;
                if (bid == 0) out[OFF_ALIGNED + row * 512 + e] = y;
            }
        }
        __syncthreads();
        {
            const float4 v = reinterpret_cast<const float4*>(sAl)[gtid & 4095];
            float4* dst = reinterpret_cast<float4*>(out + OFF_AP);
#pragma unroll 8
            for (int k2 = 0; k2 < 32; k2++) __stcs(dst + gtid + k2 * NTH, v);
        }
    }
}

// ---------------- launch ----------------
extern "C" void kernel_launch(void* const* d_in, const int* in_sizes, int n_in,
                              void* d_out, int out_size) {
    (void)in_sizes; (void)n_in; (void)out_size;
    const float* base = (const float*)d_in[0];
    const float* np_  = (const float*)d_in[1];
    const float* te   = (const float*)d_in[2];
    const float* Wt   = (const float*)d_in[3];
    const float* bt   = (const float*)d_in[4];
    const float* Wq   = (const float*)d_in[5];
    const float* bq   = (const float*)d_in[6];
    const float* Wk   = (const float*)d_in[7];
    const float* bk   = (const float*)d_in[8];
    const float* Wv   = (const float*)d_in[9];
    const float* bv   = (const float*)d_in[10];
    const float* Wo   = (const float*)d_in[11];
    const float* bo   = (const float*)d_in[12];
    const float* Wa1  = (const float*)d_in[13];
    const float* ba1  = (const float*)d_in[14];
    const float* Wa2  = (const float*)d_in[15];
    const float* ba2  = (const float*)d_in[16];
    const float* gin  = (const float*)d_in[17];
    const float* bin  = (const float*)d_in[18];
    const float* gout = (const float*)d_in[19];
    const float* bout = (const float*)d_in[20];
    float* out = (float*)d_out;

    static int attr_done = 0;
    if (!attr_done) {
        cudaFuncSetAttribute(mega, cudaFuncAttributeMaxDynamicSharedMemorySize, SMEM_BYTES);
        attr_done = 1;
    }
    mega<<<NB, NT, SMEM_BYTES>>>(base, np_, te, Wt, bt, Wq, bq, Wk, bk, Wv, bv,
                                 Wo, bo, Wa1, ba1, Wa2, ba2, gin, bin, gout, bout, out);
}

// round 13
// speedup vs baseline: 1.1273x; 1.1273x over previous
#include <cuda_runtime.h>
#include <math.h>

#define T_ 1024
#define L_ 32
#define D_ 512
#define P_ 512
#define H_ 2048
#define NB 128
#define NT 1024
#define NTH (NB * NT)   // 131072
#define SCALE_ 0.044194173824159216f  // 1/sqrt(512)
#define LN_EPS 1e-5f
#define SMEM_BYTES 70656

// output layout offsets (floats)
#define OFF_ALIGNED 0
#define OFF_AP      16384
#define OFF_TW      16793600
#define OFF_FA      16794624

// ---------------- scratch (device globals) ----------------
__device__ __align__(16) float g_bm[T_ * D_];       // base row-sums over L (NOT /32)
__device__ __align__(16) float g_rawq[L_ * P_];     // new_prompt @ Wq (no bias)
__device__ __align__(16) float g_tv[P_];            // task_vec
__device__ __align__(16) float g_pq[P_];            // pooled_q (with bias)
__device__ __align__(16) float g_u[D_];             // Wk @ task_vec
__device__ __align__(16) float g_v[D_];             // Wk @ pooled_q
__device__ __align__(16) float g_c01[2];            // c0 = bk·tv, c1 = bk·pq
__device__ __align__(16) float g_dotu[T_];
__device__ __align__(16) float g_dotv[T_];
__device__ __align__(16) float g_wcp[4 * L_ * D_];  // wc partials (4-way t)
__device__ __align__(16) float g_wc[L_ * D_];       // weighted conditioned
__device__ __align__(16) float g_wkr[L_ * P_];      // wc @ Wk (raw)
__device__ __align__(16) float g_wvr[L_ * P_];      // wc @ Wv (raw)
__device__ __align__(16) float g_oacc[L_ * D_];     // (ep+bv) @ Wo
__device__ __align__(16) float g_evolved[L_ * D_];
__device__ __align__(16) float g_h1[L_ * H_];       // evolved @ Wa1 (raw)
__device__ __align__(16) float g_mlpp[4 * L_ * D_]; // mlp partials (4-way k)

// grid barrier state
__device__ unsigned g_cnt;
__device__ unsigned g_gen;

// ---------------- grid barrier: single-thread fence ----------------
__device__ __forceinline__ void gbar() {
    __syncthreads();
    if (threadIdx.x == 0) {
        asm volatile("fence.acq_rel.gpu;" ::: "memory");
        unsigned gen = *(volatile unsigned*)&g_gen;
        if (atomicAdd(&g_cnt, 1u) == (unsigned)(NB - 1)) {
            g_cnt = 0u;
            asm volatile("fence.acq_rel.gpu;" ::: "memory");
            *(volatile unsigned*)&g_gen = gen + 1u;
        } else {
            while (*(volatile unsigned*)&g_gen == gen) __nanosleep(32);
            asm volatile("fence.acq_rel.gpu;" ::: "memory");
        }
    }
    __syncthreads();
}

// ---------------- reductions ----------------
__device__ __forceinline__ float warp_sum(float v) {
#pragma unroll
    for (int o = 16; o > 0; o >>= 1) v += __shfl_xor_sync(0xffffffffu, v, o);
    return v;
}
__device__ __forceinline__ float warp_max(float v) {
#pragma unroll
    for (int o = 16; o > 0; o >>= 1) v = fmaxf(v, __shfl_xor_sync(0xffffffffu, v, o));
    return v;
}
__device__ __forceinline__ float blk_sum(float v, float* red) {
    int w = threadIdx.x >> 5, lane = threadIdx.x & 31;
    v = warp_sum(v);
    if (lane == 0) red[w] = v;
    __syncthreads();
    if (w == 0) {
        float r = red[lane];
        r = warp_sum(r);
        if (lane == 0) red[0] = r;
    }
    __syncthreads();
    float out = red[0];
    __syncthreads();
    return out;
}
__device__ __forceinline__ float blk_max(float v, float* red) {
    int w = threadIdx.x >> 5, lane = threadIdx.x & 31;
    v = warp_max(v);
    if (lane == 0) red[w] = v;
    __syncthreads();
    if (w == 0) {
        float r = red[lane];
        r = warp_max(r);
        if (lane == 0) red[0] = r;
    }
    __syncthreads();
    float out = red[0];
    __syncthreads();
    return out;
}
__device__ __forceinline__ float dot4(float4 a, float4 b) {
    return fmaf(a.x, b.x, fmaf(a.y, b.y, fmaf(a.z, b.z, a.w * b.w)));
}

// ---------------- megakernel ----------------
__global__ void __launch_bounds__(NT, 1)
mega(const float* __restrict__ base, const float* __restrict__ np_,
     const float* __restrict__ te, const float* __restrict__ Wt,
     const float* __restrict__ bt, const float* __restrict__ Wq,
     const float* __restrict__ bq, const float* __restrict__ Wk,
     const float* __restrict__ bk, const float* __restrict__ Wv,
     const float* __restrict__ bv, const float* __restrict__ Wo,
     const float* __restrict__ bo, const float* __restrict__ Wa1,
     const float* __restrict__ ba1, const float* __restrict__ Wa2,
     const float* __restrict__ ba2, const float* __restrict__ gin,
     const float* __restrict__ bin, const float* __restrict__ gout,
     const float* __restrict__ bout, float* __restrict__ out) {
    extern __shared__ float sm[];

    const int bid = blockIdx.x;
    const int tid = threadIdx.x;
    const int gtid = bid * NT + tid;
    const int w = tid >> 5, lane = tid & 31;
    const float4* base4 = reinterpret_cast<const float4*>(base);

    // ======== S0: rawq (blk 0-7) | base row-sums (blk 8-123, DRAM pass)
    //          | tv (blk 124-125) | pq (blk 126-127)  — all concurrent
    if (bid < 8) {
        // rawq reuse-GEMM: block = (lq = bid>>1, ph = bid&1); 8 l-rows x 256 p-cols
        float* npS = sm;           // 8 x 512
        float* sPart = sm + 4096;  // 4 x 2048
        int lq = bid >> 1, ph = bid & 1;
        for (int i = tid; i < 4096; i += NT) {
            int l = i >> 9, k = i & 511;
            npS[i] = np_[(lq * 8 + l) * 512 + k];
        }
        __syncthreads();
        int poff = tid & 255, sub = tid >> 8;   // sub: 4-way k-split of 128
        const float* wq = Wq + (size_t)(sub * 128) * P_ + ph * 256 + poff;
        float acc[8] = {0.f, 0.f, 0.f, 0.f, 0.f, 0.f, 0.f, 0.f};
        const float* nr = npS + sub * 128;
#pragma unroll 4
        for (int kk = 0; kk < 128; kk++) {
            float wv = wq[(size_t)kk * P_];
#pragma unroll
            for (int l = 0; l < 8; l++) acc[l] = fmaf(nr[l * 512 + kk], wv, acc[l]);
        }
#pragma unroll
        for (int l = 0; l < 8; l++) sPart[sub * 2048 + poff * 8 + l] = acc[l];
        __syncthreads();
        for (int m = tid; m < 2048; m += NT) {
            float val = sPart[m] + sPart[2048 + m] + sPart[4096 + m] + sPart[6144 + m];
            int l = m & 7, po = m >> 3;
            g_rawq[(lq * 8 + l) * 512 + ph * 256 + po] = val;
        }
    } else if (bid < 124) {
        // base row-sums over L (raw, no /32): THE DRAM pass
        for (int i = (bid - 8) * NT + tid; i < 131072; i += 116 * NT) {
            int t = i >> 7, c = i & 127;
            const float4* p = base4 + (size_t)t * 4096 + c;
            float4 s = {0.f, 0.f, 0.f, 0.f};
#pragma unroll 8
            for (int l = 0; l < L_; l++) {
                float4 b4 = p[l * 128];
                s.x += b4.x; s.y += b4.y; s.z += b4.z; s.w += b4.w;
            }
            reinterpret_cast<float4*>(g_bm)[i] = s;
        }
    } else if (bid < 126) {
        // tv = tanh(te @ Wt + bt): block q handles 256 p-cols
        float* teS = sm;           // 512
        float* sPart = sm + 512;   // 1024
        int q = bid - 124;
        if (tid < 512) teS[tid] = te[tid];
        __syncthreads();
        int poff = tid & 255, sub = tid >> 8;
        int p = q * 256 + poff;
        const float* wcol = Wt + (size_t)(sub * 128) * P_ + p;
        const float* tr = teS + sub * 128;
        float a = 0.f;
#pragma unroll 8
        for (int kk = 0; kk < 128; kk++) a = fmaf(tr[kk], wcol[(size_t)kk * P_], a);
        sPart[sub * 256 + poff] = a;
        __syncthreads();
        if (tid < 256) {
            int p2 = q * 256 + tid;
            float v = sPart[tid] + sPart[256 + tid] + sPart[512 + tid] + sPart[768 + tid];
            g_tv[p2] = tanhf(v + bt[p2]);
        }
    } else {
        // pq = (mean_l np) @ Wq + bq: block q handles 256 p-cols
        float* nmS = sm;           // 512
        float* sPart = sm + 512;   // 1024
        int q = bid - 126;
        if (tid < 512) {
            float s = 0.f;
#pragma unroll 8
            for (int l = 0; l < 32; l++) s += np_[l * 512 + tid];
            nmS[tid] = s * (1.f / 32.f);
        }
        __syncthreads();
        int poff = tid & 255, sub = tid >> 8;
        int p = q * 256 + poff;
        const float* wcol = Wq + (size_t)(sub * 128) * P_ + p;
        const float* nr = nmS + sub * 128;
        float a = 0.f;
#pragma unroll 8
        for (int kk = 0; kk < 128; kk++) a = fmaf(nr[kk], wcol[(size_t)kk * P_], a);
        sPart[sub * 256 + poff] = a;
        __syncthreads();
        if (tid < 256) {
            int p2 = q * 256 + tid;
            float v = sPart[tid] + sPart[256 + tid] + sPart[512 + tid] + sPart[768 + tid];
            g_pq[p2] = v + bq[p2];
        }
    }
    gbar();

    // ======== S1: u,v (blk 0-31, warp-per-row) + c0,c1 (blk 32)
    if (bid < 32) {
        float* sTV = sm;          // 512
        float* sPQ = sm + 512;    // 512
        if (tid < 512) sTV[tid] = g_tv[tid];
        else sPQ[tid - 512] = g_pq[tid - 512];
        __syncthreads();
        const float4* tv4 = reinterpret_cast<const float4*>(sTV);
        const float4* pq4 = reinterpret_cast<const float4*>(sPQ);
        int d = bid * 16 + (w & 15);
        const float4* row = reinterpret_cast<const float4*>(Wk + (size_t)d * P_);
        const float4* xv = (w < 16) ? tv4 : pq4;
        float a = 0.f;
#pragma unroll
        for (int i = 0; i < 4; i++) a += dot4(row[lane + 32 * i], xv[lane + 32 * i]);
        a = warp_sum(a);
        if (lane == 0) {
            if (w < 16) g_u[d] = a;
            else        g_v[d] = a;
        }
    } else if (bid == 32) {
        float* sRed = sm;  // 32
        float t0 = (tid < 512) ? bk[tid] * g_tv[tid] : 0.f;
        float c0 = blk_sum(t0, sRed);
        float t1 = (tid < 512) ? bk[tid] * g_pq[tid] : 0.f;
        float c1 = blk_sum(t1, sRed);
        if (tid == 0) { g_c01[0] = c0; g_c01[1] = c1; }
    }
    gbar();

    // ======== S2: dots from g_bm (all blocks; tiny 2MB pass; fold 1/32 here)
    {
        float4* sU4 = reinterpret_cast<float4*>(sm);         // 128
        float4* sV4 = reinterpret_cast<float4*>(sm) + 128;   // 128
        float* sPu = sm + 1024;  // 32
        float* sPv = sm + 1056;  // 32
        if (tid < 128) sU4[tid] = reinterpret_cast<const float4*>(g_u)[tid];
        else if (tid < 256) sV4[tid - 128] = reinterpret_cast<const float4*>(g_v)[tid - 128];
        __syncthreads();
        int t = bid * 8 + (w >> 2);
        int seg = w & 3;
        float4 b4 = reinterpret_cast<const float4*>(g_bm)[t * 128 + seg * 32 + lane];
        float au = dot4(b4, sU4[seg * 32 + lane]);
        float av = dot4(b4, sV4[seg * 32 + lane]);
        au = warp_sum(au);
        av = warp_sum(av);
        if (lane == 0) { sPu[w] = au; sPv[w] = av; }
        __syncthreads();
        if (tid < 8) {
            float su = sPu[4 * tid] + sPu[4 * tid + 1] + sPu[4 * tid + 2] + sPu[4 * tid + 3];
            g_dotu[bid * 8 + tid] = su * (1.f / 32.f);
        } else if (tid < 16) {
            int q = tid - 8;
            float sv = sPv[4 * q] + sPv[4 * q + 1] + sPv[4 * q + 2] + sPv[4 * q + 3];
            g_dotv[bid * 8 + q] = sv * (1.f / 32.f);
        }
    }
    gbar();

    // ======== S3: task softmaxes (redundant; tid==t) + wc partials (base from L2)
    {
        float* sC = sm;                // 1024 coef
        float* sRed = sm + 1024;       // 32
        float4* sP4 = reinterpret_cast<float4*>(sm + 1056); // 1024 float4

        float c0 = g_c01[0], c1 = g_c01[1];

        float s1 = SCALE_ * (g_dotu[tid] + c0);
        float dv = g_dotv[tid];
        float m1 = blk_max(s1, sRed);
        float e1 = expf(s1 - m1);
        float tw1 = e1 / blk_sum(e1, sRed);

        float s2 = SCALE_ * ((1.f + tw1) * dv + c1);
        float m2 = blk_max(s2, sRed);
        float e2 = expf(s2 - m2);
        float ta = e2 / blk_sum(e2, sRed);

        float tw = 0.5f * (tw1 + ta);
        float S = blk_sum(tw, sRed);
        float tw2 = tw / fmaxf(S, 1e-6f);
        sC[tid] = tw2 * (1.f + tw1);
        if (bid == 0) out[OFF_TW + tid] = tw2;
        __syncthreads();

        int l = bid >> 2, q = bid & 3;
        int c = tid & 127, ts = tid >> 7;       // ts 0..7
        int t0 = q * 256 + ts * 32;
        const float4* bp = base4 + (size_t)t0 * 4096 + l * 128 + c;
        const float* cf = sC + t0;
        float4 acc = {0.f, 0.f, 0.f, 0.f};
#pragma unroll 8
        for (int i = 0; i < 32; i++) {
            float cv = cf[i];
            float4 b4 = bp[i * 4096];
            acc.x = fmaf(cv, b4.x, acc.x);
            acc.y = fmaf(cv, b4.y, acc.y);
            acc.z = fmaf(cv, b4.z, acc.z);
            acc.w = fmaf(cv, b4.w, acc.w);
        }
        sP4[ts * 128 + c] = acc;
        __syncthreads();
        if (tid < 128) {
            float4 a = sP4[tid];
#pragma unroll
            for (int g2 = 1; g2 < 8; g2++) {
                float4 b = sP4[g2 * 128 + tid];
                a.x += b.x; a.y += b.y; a.z += b.z; a.w += b.w;
            }
            reinterpret_cast<float4*>(g_wcp)[q * 4096 + l * 128 + tid] = a;
        }
    }
    gbar();

    // ======== S4: fold wc (redundant) + wkr/wvr column-strip GEMM (all blocks)
    {
        float* sX = sm;               // 32 x 513 padded
        float* sPart = sm + 16416;    // 1024
        const float* W = (bid < 64) ? Wk : Wv;
        int colbase = (bid & 63) * 8;
        for (int i = tid; i < 16384; i += NT) {
            float x = g_wcp[i] + g_wcp[16384 + i] + g_wcp[32768 + i] + g_wcp[49152 + i];
            int l = i >> 9, k = i & 511;
            sX[l * 513 + k] = x;
            if (bid == 0) g_wc[i] = x;
        }
        __syncthreads();
        int o = tid & 255;
        int l = o >> 3, dd = o & 7;
        int kq = tid >> 8;                  // 0..3
        const float* xr = sX + l * 513 + kq * 128;
        const float* wcol = W + (size_t)(kq * 128) * P_ + colbase + dd;
        float a0 = 0.f, a1 = 0.f;
#pragma unroll 8
        for (int k = 0; k < 128; k += 2) {
            a0 = fmaf(xr[k], wcol[(size_t)k * P_], a0);
            a1 = fmaf(xr[k + 1], wcol[(size_t)(k + 1) * P_], a1);
        }
        sPart[kq * 256 + o] = a0 + a1;
        __syncthreads();
        if (tid < 256) {
            float v = sPart[tid] + sPart[256 + tid] + sPart[512 + tid] + sPart[768 + tid];
            int ll = tid >> 3, d2 = tid & 7;
            if (bid < 64) g_wkr[ll * 512 + colbase + d2] = v;
            else          g_wvr[ll * 512 + colbase + d2] = v;
        }
    }
    gbar();

    // ======== S5: flog + softmax + ep + oacc (block = (l = bid>>2, dq = bid&3))
    {
        float* sF = sm;          // 32
        float* sFa = sm + 32;    // 32
        float* sE = sm + 64;     // 512
        float* sP = sm + 576;    // 1024
        int l = bid >> 2, dq = bid & 3;
        const float* qr = g_rawq + l * P_;
        {
            const float* kr = g_wkr + w * P_;
            float a = 0.f;
#pragma unroll
            for (int i = 0; i < 16; i++) {
                int e = lane + 32 * i;
                a = fmaf(qr[e] + bq[e], kr[e] + bk[e], a);
            }
            a = warp_sum(a);
            if (lane == 0) sF[w] = SCALE_ * a;
        }
        __syncthreads();
        if (w == 0) {
            float x = sF[lane];
            float m = warp_max(x);
            float e = expf(x - m);
            float s = warp_sum(e);
            float f = e / s;
            sFa[lane] = f;
            if (dq == 0) out[OFF_FA + l * 32 + lane] = f;
        }
        __syncthreads();
        if (tid < 512) {
            float a = bv[tid];
#pragma unroll
            for (int j = 0; j < 32; j++) a = fmaf(sFa[j], g_wvr[j * P_ + tid], a);
            sE[tid] = a;
        }
        __syncthreads();
        {
            int dd = tid & 127, ks = tid >> 7;  // ks 0..7
            int d = dq * 128 + dd;
            const float* wcol = Wo + (size_t)(ks * 64) * D_ + d;
            const float* er = sE + ks * 64;
            float a0 = 0.f, a1 = 0.f;
#pragma unroll 8
            for (int k = 0; k < 64; k += 2) {
                a0 = fmaf(er[k], wcol[(size_t)k * D_], a0);
                a1 = fmaf(er[k + 1], wcol[(size_t)(k + 1) * D_], a1);
            }
            sP[ks * 128 + dd] = a0 + a1;
        }
        __syncthreads();
        if (tid < 128) {
            float v = 0.f;
#pragma unroll
            for (int g2 = 0; g2 < 8; g2++) v += sP[g2 * 128 + tid];
            g_oacc[l * 512 + dq * 128 + tid] = v;
        }
    }
    gbar();

    // ======== S6: LN1 (redundant, warp-per-row) + h1 strip GEMM (all blocks)
    {
        float* sEvo = sm;             // 32 x 513
        float* sPart = sm + 16416;    // 1024
        {
            int row = w;
            float x[16];
            float s = 0.f;
#pragma unroll
            for (int i = 0; i < 16; i++) {
                int e = lane + 32 * i;
                x[i] = g_wc[row * 512 + e] + g_oacc[row * 512 + e] + bo[e];
                s += x[i];
            }
            float mean = warp_sum(s) * (1.f / D_);
            float v = 0.f;
#pragma unroll
            for (int i = 0; i < 16; i++) { float d = x[i] - mean; v = fmaf(d, d, v); }
            float inv = rsqrtf(warp_sum(v) * (1.f / D_) + LN_EPS);
#pragma unroll
            for (int i = 0; i < 16; i++) {
                int e = lane + 32 * i;
                float y = (x[i] - mean) * inv * gin[e] + bin[e];
                sEvo[row * 513 + e] = y;
                if (bid == 0) g_evolved[row * 512 + e] = y;
            }
        }
        __syncthreads();
        {
            int dd = w & 15, kh = w >> 4;
            int p = bid * 16 + dd;
            const float* xr = sEvo + lane * 513 + kh * 256;
            const float* wcol = Wa1 + (size_t)(kh * 256) * H_ + p;
            float a0 = 0.f, a1 = 0.f;
#pragma unroll 8
            for (int k = 0; k < 256; k += 2) {
                a0 = fmaf(xr[k], wcol[(size_t)k * H_], a0);
                a1 = fmaf(xr[k + 1], wcol[(size_t)(k + 1) * H_], a1);
            }
            sPart[kh * 512 + lane * 16 + dd] = a0 + a1;
        }
        __syncthreads();
        if (tid < 512) {
            int l = tid >> 4, dd = tid & 15;
            g_h1[l * H_ + bid * 16 + dd] = sPart[tid] + sPart[512 + tid];
        }
    }
    gbar();

    // ======== S7: mlp strip GEMM (block = (ks = bid&3, dseg = bid>>2))
    {
        float* sH = sm;               // 32 x 513
        float* sPart = sm + 16416;    // 1024
        int ks = bid & 3, dseg = bid >> 2;
        for (int i = tid; i < 16384; i += NT) {
            int row = i >> 9, k = i & 511;
            int kg = ks * 512 + k;
            sH[row * 513 + k] = fmaxf(g_h1[row * H_ + kg] + ba1[kg], 0.f);
        }
        __syncthreads();
        {
            int dd = w & 15, kh = w >> 4;
            int d = dseg * 16 + dd;
            const float* hr = sH + lane * 513 + kh * 256;
            const float* wcol = Wa2 + (size_t)(ks * 512 + kh * 256) * D_ + d;
            float a0 = 0.f, a1 = 0.f;
#pragma unroll 8
            for (int k = 0; k < 256; k += 2) {
                a0 = fmaf(hr[k], wcol[(size_t)k * D_], a0);
                a1 = fmaf(hr[k + 1], wcol[(size_t)(k + 1) * D_], a1);
            }
            sPart[kh * 512 + lane * 16 + dd] = a0 + a1;
        }
        __syncthreads();
        if (tid < 512) {
            int l = tid >> 4, dd = tid & 15;
            g_mlpp[ks * 16384 + l * 512 + dseg * 16 + dd] = sPart[tid] + sPart[512 + tid];
        }
    }
    gbar();

    // ======== S8: LN2 (redundant, warp-per-row) + broadcast (all blocks)
    {
        float* sAl = sm;   // 16384
        {
            int row = w;
            float x[16];
            float s = 0.f;
#pragma unroll
            for (int i = 0; i < 16; i++) {
                int e = lane + 32 * i;
                int o = row * 512 + e;
                x[i] = g_evolved[o] + g_mlpp[o] + g_mlpp[16384 + o] +
                       g_mlpp[32768 + o] + g_mlpp[49152 + o] + ba2[e];
                s += x[i];
            }
            float mean = warp_sum(s) * (1.f / D_);
            float v = 0.f;
#pragma unroll
            for (int i = 0; i < 16; i++) { float d = x[i] - mean; v = fmaf(d, d, v); }
            float inv = rsqrtf(warp_sum(v) * (1.f / D_) + LN_EPS);
#pragma unroll
            for (int i = 0; i < 16; i++) {
                int e = lane + 32 * i;
                float y = (x[i] - mean) * inv * gout[e] + bout[e];
                sAl[row * 512 + e] = y;
                if (bid == 0) out[OFF_ALIGNED + row * 512 + e] = y;
            }
        }
        __syncthreads();
        {
            const float4 v = reinterpret_cast<const float4*>(sAl)[gtid & 4095];
            float4* dst = reinterpret_cast<float4*>(out + OFF_AP);
#pragma unroll 8
            for (int k2 = 0; k2 < 32; k2++) __stcs(dst + gtid + k2 * NTH, v);
        }
    }
}

// ---------------- launch ----------------
extern "C" void kernel_launch(void* const* d_in, const int* in_sizes, int n_in,
                              void* d_out, int out_size) {
    (void)in_sizes; (void)n_in; (void)out_size;
    const float* base = (const float*)d_in[0];
    const float* np_  = (const float*)d_in[1];
    const float* te   = (const float*)d_in[2];
    const float* Wt   = (const float*)d_in[3];
    const float* bt   = (const float*)d_in[4];
    const float* Wq   = (const float*)d_in[5];
    const float* bq   = (const float*)d_in[6];
    const float* Wk   = (const float*)d_in[7];
    const float* bk   = (const float*)d_in[8];
    const float* Wv   = (const float*)d_in[9];
    const float* bv   = (const float*)d_in[10];
    const float* Wo   = (const float*)d_in[11];
    const float* bo   = (const float*)d_in[12];
    const float* Wa1  = (const float*)d_in[13];
    const float* ba1  = (const float*)d_in[14];
    const float* Wa2  = (const float*)d_in[15];
    const float* ba2  = (const float*)d_in[16];
    const float* gin  = (const float*)d_in[17];
    const float* bin  = (const float*)d_in[18];
    const float* gout = (const float*)d_in[19];
    const float* bout = (const float*)d_in[20];
    float* out = (float*)d_out;

    static int attr_done = 0;
    if (!attr_done) {
        cudaFuncSetAttribute(mega, cudaFuncAttributeMaxDynamicSharedMemorySize, SMEM_BYTES);
        attr_done = 1;
    }
    mega<<<NB, NT, SMEM_BYTES>>>(base, np_, te, Wt, bt, Wq, bq, Wk, bk, Wv, bv,
                                 Wo, bo, Wa1, ba1, Wa2, ba2, gin, bin, gout, bout, out);
}

// round 15
// speedup vs baseline: 1.1329x; 1.0050x over previous
#include <cuda_runtime.h>
#include <math.h>

#define T_ 1024
#define L_ 32
#define D_ 512
#define P_ 512
#define H_ 2048
#define NB 128
#define NT 1024
#define NTH (NB * NT)   // 131072
#define SCALE_ 0.044194173824159216f  // 1/sqrt(512)
#define LN_EPS 1e-5f
#define SMEM_BYTES 70656

// output layout offsets (floats)
#define OFF_ALIGNED 0
#define OFF_AP      16384
#define OFF_TW      16793600
#define OFF_FA      16794624

// ---------------- scratch (device globals) ----------------
__device__ __align__(16) float g_bm[T_ * D_];       // base row-sums over L (NOT /32)
__device__ __align__(16) float g_rawq[L_ * P_];     // new_prompt @ Wq (no bias)
__device__ __align__(16) float g_tv[P_];            // task_vec
__device__ __align__(16) float g_pq[P_];            // pooled_q (with bias)
__device__ __align__(16) float g_u[D_];             // Wk @ task_vec
__device__ __align__(16) float g_v[D_];             // Wk @ pooled_q
__device__ __align__(16) float g_c01[2];            // c0 = bk·tv, c1 = bk·pq
__device__ __align__(16) float g_dotu[T_];
__device__ __align__(16) float g_dotv[T_];
__device__ __align__(16) float g_wcp[4 * L_ * D_];  // wc partials (4-way t)
__device__ __align__(16) float g_wc[L_ * D_];       // weighted conditioned
__device__ __align__(16) float g_wkr[L_ * P_];      // wc @ Wk (raw)
__device__ __align__(16) float g_wvr[L_ * P_];      // wc @ Wv (raw)
__device__ __align__(16) float g_oacc[L_ * D_];     // (ep+bv) @ Wo
__device__ __align__(16) float g_evolved[L_ * D_];
__device__ __align__(16) float g_h1[L_ * H_];       // evolved @ Wa1 (raw)
__device__ __align__(16) float g_mlpp[4 * L_ * D_]; // mlp partials (4-way k)

// grid barrier state
__device__ unsigned g_cnt;
__device__ unsigned g_gen;
// sub-group barrier (blocks 116..127)
__device__ unsigned g_cnt2;
__device__ unsigned g_gen2;

// ---------------- grid barrier: single-thread fence ----------------
__device__ __forceinline__ void gbar() {
    __syncthreads();
    if (threadIdx.x == 0) {
        asm volatile("fence.acq_rel.gpu;" ::: "memory");
        unsigned gen = *(volatile unsigned*)&g_gen;
        if (atomicAdd(&g_cnt, 1u) == (unsigned)(NB - 1)) {
            g_cnt = 0u;
            asm volatile("fence.acq_rel.gpu;" ::: "memory");
            *(volatile unsigned*)&g_gen = gen + 1u;
        } else {
            while (*(volatile unsigned*)&g_gen == gen) __nanosleep(32);
            asm volatile("fence.acq_rel.gpu;" ::: "memory");
        }
    }
    __syncthreads();
}

// 12-block sub-barrier (only blocks 116..127 call this)
__device__ __forceinline__ void sub_gbar() {
    __syncthreads();
    if (threadIdx.x == 0) {
        asm volatile("fence.acq_rel.gpu;" ::: "memory");
        unsigned gen = *(volatile unsigned*)&g_gen2;
        if (atomicAdd(&g_cnt2, 1u) == 11u) {
            g_cnt2 = 0u;
            asm volatile("fence.acq_rel.gpu;" ::: "memory");
            *(volatile unsigned*)&g_gen2 = gen + 1u;
        } else {
            while (*(volatile unsigned*)&g_gen2 == gen) __nanosleep(32);
            asm volatile("fence.acq_rel.gpu;" ::: "memory");
        }
    }
    __syncthreads();
}

// ---------------- reductions ----------------
__device__ __forceinline__ float warp_sum(float v) {
#pragma unroll
    for (int o = 16; o > 0; o >>= 1) v += __shfl_xor_sync(0xffffffffu, v, o);
    return v;
}
__device__ __forceinline__ float warp_max(float v) {
#pragma unroll
    for (int o = 16; o > 0; o >>= 1) v = fmaxf(v, __shfl_xor_sync(0xffffffffu, v, o));
    return v;
}
__device__ __forceinline__ float blk_sum(float v, float* red) {
    int w = threadIdx.x >> 5, lane = threadIdx.x & 31;
    v = warp_sum(v);
    if (lane == 0) red[w] = v;
    __syncthreads();
    if (w == 0) {
        float r = red[lane];
        r = warp_sum(r);
        if (lane == 0) red[0] = r;
    }
    __syncthreads();
    float out = red[0];
    __syncthreads();
    return out;
}
__device__ __forceinline__ float blk_max(float v, float* red) {
    int w = threadIdx.x >> 5, lane = threadIdx.x & 31;
    v = warp_max(v);
    if (lane == 0) red[w] = v;
    __syncthreads();
    if (w == 0) {
        float r = red[lane];
        r = warp_max(r);
        if (lane == 0) red[0] = r;
    }
    __syncthreads();
    float out = red[0];
    __syncthreads();
    return out;
}
__device__ __forceinline__ float dot4(float4 a, float4 b) {
    return fmaf(a.x, b.x, fmaf(a.y, b.y, fmaf(a.z, b.z, a.w * b.w)));
}
__device__ __forceinline__ void l2_prefetch(const void* p) {
    asm volatile("prefetch.global.L2 [%0];" :: "l"(p));
}

// ---------------- megakernel ----------------
__global__ void __launch_bounds__(NT, 1)
mega(const float* __restrict__ base, const float* __restrict__ np_,
     const float* __restrict__ te, const float* __restrict__ Wt,
     const float* __restrict__ bt, const float* __restrict__ Wq,
     const float* __restrict__ bq, const float* __restrict__ Wk,
     const float* __restrict__ bk, const float* __restrict__ Wv,
     const float* __restrict__ bv, const float* __restrict__ Wo,
     const float* __restrict__ bo, const float* __restrict__ Wa1,
     const float* __restrict__ ba1, const float* __restrict__ Wa2,
     const float* __restrict__ ba2, const float* __restrict__ gin,
     const float* __restrict__ bin, const float* __restrict__ gout,
     const float* __restrict__ bout, float* __restrict__ out) {
    extern __shared__ float sm[];

    const int bid = blockIdx.x;
    const int tid = threadIdx.x;
    const int gtid = bid * NT + tid;
    const int w = tid >> 5, lane = tid & 31;
    const float4* base4 = reinterpret_cast<const float4*>(base);

    // ======== S0 (one global stage, three concurrent roles):
    //   blk 0-7:    rawq reuse-GEMM
    //   blk 8-115:  L2-prefetch weights + base row-sums (THE DRAM pass)
    //   blk 116-127: tv/pq -> sub-barrier -> u,v + c0,c1 (hidden under stream)
    if (bid < 8) {
        float* npS = sm;           // 8 x 512
        float* sPart = sm + 4096;  // 4 x 2048
        int lq = bid >> 1, ph = bid & 1;
        for (int i = tid; i < 4096; i += NT) {
            int l = i >> 9, k = i & 511;
            npS[i] = np_[(lq * 8 + l) * 512 + k];
        }
        __syncthreads();
        int poff = tid & 255, sub = tid >> 8;   // 4-way k-split of 512
        const float* wq = Wq + (size_t)(sub * 128) * P_ + ph * 256 + poff;
        float acc[8] = {0.f, 0.f, 0.f, 0.f, 0.f, 0.f, 0.f, 0.f};
        const float* nr = npS + sub * 128;
#pragma unroll 4
        for (int kk = 0; kk < 128; kk++) {
            float wv = wq[(size_t)kk * P_];
#pragma unroll
            for (int l = 0; l < 8; l++) acc[l] = fmaf(nr[l * 512 + kk], wv, acc[l]);
        }
#pragma unroll
        for (int l = 0; l < 8; l++) sPart[sub * 2048 + poff * 8 + l] = acc[l];
        __syncthreads();
        for (int m = tid; m < 2048; m += NT) {
            float val = sPart[m] + sPart[2048 + m] + sPart[4096 + m] + sPart[6144 + m];
            int l = m & 7, po = m >> 3;
            g_rawq[(lq * 8 + l) * 512 + ph * 256 + po] = val;
        }
    } else if (bid < 116) {
        // L2 prefetch of cold weights (11MB total; ~1 line/thread), then stream base
        {
            int j = (bid - 8) * NT + tid;   // line id, 128B lines
            // cumulative lines: Wa1 32768 | Wa2 32768 | Wo 8192 | Wk 8192 | Wv 8192
            if (j < 32768) l2_prefetch((const char*)Wa1 + (size_t)j * 128);
            else if (j < 65536) l2_prefetch((const char*)Wa2 + (size_t)(j - 32768) * 128);
            else if (j < 73728) l2_prefetch((const char*)Wo + (size_t)(j - 65536) * 128);
            else if (j < 81920) l2_prefetch((const char*)Wk + (size_t)(j - 73728) * 128);
            else if (j < 90112) l2_prefetch((const char*)Wv + (size_t)(j - 81920) * 128);
        }
        for (int i = (bid - 8) * NT + tid; i < 131072; i += 108 * NT) {
            int t = i >> 7, c = i & 127;
            const float4* p = base4 + (size_t)t * 4096 + c;
            float4 s = {0.f, 0.f, 0.f, 0.f};
#pragma unroll 8
            for (int l = 0; l < L_; l++) {
                float4 b4 = p[l * 128];
                s.x += b4.x; s.y += b4.y; s.z += b4.z; s.w += b4.w;
            }
            reinterpret_cast<float4*>(g_bm)[i] = s;
        }
    } else {
        // chain blocks 116..127
        if (bid < 118) {
            // tv = tanh(te @ Wt + bt): block q handles 256 p-cols
            float* teS = sm;           // 512
            float* sPart = sm + 512;   // 1024
            int q = bid - 116;
            if (tid < 512) teS[tid] = te[tid];
            __syncthreads();
            int poff = tid & 255, sub = tid >> 8;
            int p = q * 256 + poff;
            const float* wcol = Wt + (size_t)(sub * 128) * P_ + p;
            const float* tr = teS + sub * 128;
            float a = 0.f;
#pragma unroll 8
            for (int kk = 0; kk < 128; kk++) a = fmaf(tr[kk], wcol[(size_t)kk * P_], a);
            sPart[sub * 256 + poff] = a;
            __syncthreads();
            if (tid < 256) {
                int p2 = q * 256 + tid;
                float v = sPart[tid] + sPart[256 + tid] + sPart[512 + tid] + sPart[768 + tid];
                g_tv[p2] = tanhf(v + bt[p2]);
            }
        } else if (bid < 120) {
            // pq = (mean_l np) @ Wq + bq: block q handles 256 p-cols
            float* nmS = sm;           // 512
            float* sPart = sm + 512;   // 1024
            int q = bid - 118;
            if (tid < 512) {
                float s = 0.f;
#pragma unroll 8
                for (int l = 0; l < 32; l++) s += np_[l * 512 + tid];
                nmS[tid] = s * (1.f / 32.f);
            }
            __syncthreads();
            int poff = tid & 255, sub = tid >> 8;
            int p = q * 256 + poff;
            const float* wcol = Wq + (size_t)(sub * 128) * P_ + p;
            const float* nr = nmS + sub * 128;
            float a = 0.f;
#pragma unroll 8
            for (int kk = 0; kk < 128; kk++) a = fmaf(nr[kk], wcol[(size_t)kk * P_], a);
            sPart[sub * 256 + poff] = a;
            __syncthreads();
            if (tid < 256) {
                int p2 = q * 256 + tid;
                float v = sPart[tid] + sPart[256 + tid] + sPart[512 + tid] + sPart[768 + tid];
                g_pq[p2] = v + bq[p2];
            }
        }
        sub_gbar();
        // phase 2: u,v over 12 blocks (warp-per-row), c0/c1 on block 127
        {
            float* sTV = sm;          // 512
            float* sPQ = sm + 512;    // 512
            float* sRed = sm + 1024;  // 32
            if (tid < 512) sTV[tid] = g_tv[tid];
            else if (tid < 1024) sPQ[tid - 512] = g_pq[tid - 512];
            __syncthreads();
            const float4* tv4 = reinterpret_cast<const float4*>(sTV);
            const float4* pq4 = reinterpret_cast<const float4*>(sPQ);
            for (int tk = (bid - 116) * 32 + w; tk < 1024; tk += 384) {
                int sel = tk >> 9, d = tk & 511;
                const float4* row = reinterpret_cast<const float4*>(Wk + (size_t)d * P_);
                const float4* xv = sel ? pq4 : tv4;
                float a = 0.f;
#pragma unroll
                for (int i = 0; i < 4; i++) a += dot4(row[lane + 32 * i], xv[lane + 32 * i]);
                a = warp_sum(a);
                if (lane == 0) { if (sel) g_v[d] = a; else g_u[d] = a; }
            }
            if (bid == 127) {
                float t0 = (tid < 512) ? bk[tid] * sTV[tid] : 0.f;
                float c0 = blk_sum(t0, sRed);
                float t1 = (tid < 512) ? bk[tid] * sPQ[tid] : 0.f;
                float c1 = blk_sum(t1, sRed);
                if (tid == 0) { g_c01[0] = c0; g_c01[1] = c1; }
            }
        }
    }
    gbar();

    // ======== S1: dots from g_bm (all blocks; tiny 2MB pass; fold 1/32 here)
    {
        float4* sU4 = reinterpret_cast<float4*>(sm);         // 128
        float4* sV4 = reinterpret_cast<float4*>(sm) + 128;   // 128
        float* sPu = sm + 1024;  // 32
        float* sPv = sm + 1056;  // 32
        if (tid < 128) sU4[tid] = reinterpret_cast<const float4*>(g_u)[tid];
        else if (tid < 256) sV4[tid - 128] = reinterpret_cast<const float4*>(g_v)[tid - 128];
        __syncthreads();
        int t = bid * 8 + (w >> 2);
        int seg = w & 3;
        float4 b4 = reinterpret_cast<const float4*>(g_bm)[t * 128 + seg * 32 + lane];
        float au = dot4(b4, sU4[seg * 32 + lane]);
        float av = dot4(b4, sV4[seg * 32 + lane]);
        au = warp_sum(au);
        av = warp_sum(av);
        if (lane == 0) { sPu[w] = au; sPv[w] = av; }
        __syncthreads();
        if (tid < 8) {
            float su = sPu[4 * tid] + sPu[4 * tid + 1] + sPu[4 * tid + 2] + sPu[4 * tid + 3];
            g_dotu[bid * 8 + tid] = su * (1.f / 32.f);
        } else if (tid < 16) {
            int q = tid - 8;
            float sv = sPv[4 * q] + sPv[4 * q + 1] + sPv[4 * q + 2] + sPv[4 * q + 3];
            g_dotv[bid * 8 + q] = sv * (1.f / 32.f);
        }
    }
    gbar();

    // ======== S2: task softmaxes (redundant; tid==t) + wc partials (base from L2)
    {
        float* sC = sm;                // 1024 coef
        float* sRed = sm + 1024;       // 32
        float4* sP4 = reinterpret_cast<float4*>(sm + 1056); // 1024 float4

        float c0 = g_c01[0], c1 = g_c01[1];

        float s1 = SCALE_ * (g_dotu[tid] + c0);
        float dv = g_dotv[tid];
        float m1 = blk_max(s1, sRed);
        float e1 = expf(s1 - m1);
        float tw1 = e1 / blk_sum(e1, sRed);

        float s2 = SCALE_ * ((1.f + tw1) * dv + c1);
        float m2 = blk_max(s2, sRed);
        float e2 = expf(s2 - m2);
        float ta = e2 / blk_sum(e2, sRed);

        float tw = 0.5f * (tw1 + ta);
        float S = blk_sum(tw, sRed);
        float tw2 = tw / fmaxf(S, 1e-6f);
        sC[tid] = tw2 * (1.f + tw1);
        if (bid == 0) out[OFF_TW + tid] = tw2;
        __syncthreads();

        int l = bid >> 2, q = bid & 3;
        int c = tid & 127, ts = tid >> 7;       // ts 0..7
        int t0 = q * 256 + ts * 32;
        const float4* bp = base4 + (size_t)t0 * 4096 + l * 128 + c;
        const float* cf = sC + t0;
        float4 acc = {0.f, 0.f, 0.f, 0.f};
#pragma unroll 8
        for (int i = 0; i < 32; i++) {
            float cv = cf[i];
            float4 b4 = bp[i * 4096];
            acc.x = fmaf(cv, b4.x, acc.x);
            acc.y = fmaf(cv, b4.y, acc.y);
            acc.z = fmaf(cv, b4.z, acc.z);
            acc.w = fmaf(cv, b4.w, acc.w);
        }
        sP4[ts * 128 + c] = acc;
        __syncthreads();
        if (tid < 128) {
            float4 a = sP4[tid];
#pragma unroll
            for (int g2 = 1; g2 < 8; g2++) {
                float4 b = sP4[g2 * 128 + tid];
                a.x += b.x; a.y += b.y; a.z += b.z; a.w += b.w;
            }
            reinterpret_cast<float4*>(g_wcp)[q * 4096 + l * 128 + tid] = a;
        }
    }
    gbar();

    // ======== S3: fold wc (redundant) + wkr/wvr column-strip GEMM (all blocks)
    {
        float* sX = sm;               // 32 x 513 padded
        float* sPart = sm + 16416;    // 1024
        const float* W = (bid < 64) ? Wk : Wv;
        int colbase = (bid & 63) * 8;
        for (int i = tid; i < 16384; i += NT) {
            float x = g_wcp[i] + g_wcp[16384 + i] + g_wcp[32768 + i] + g_wcp[49152 + i];
            int l = i >> 9, k = i & 511;
            sX[l * 513 + k] = x;
            if (bid == 0) g_wc[i] = x;
        }
        __syncthreads();
        int o = tid & 255;
        int l = o >> 3, dd = o & 7;
        int kq = tid >> 8;                  // 0..3
        const float* xr = sX + l * 513 + kq * 128;
        const float* wcol = W + (size_t)(kq * 128) * P_ + colbase + dd;
        float a0 = 0.f, a1 = 0.f;
#pragma unroll 8
        for (int k = 0; k < 128; k += 2) {
            a0 = fmaf(xr[k], wcol[(size_t)k * P_], a0);
            a1 = fmaf(xr[k + 1], wcol[(size_t)(k + 1) * P_], a1);
        }
        sPart[kq * 256 + o] = a0 + a1;
        __syncthreads();
        if (tid < 256) {
            float v = sPart[tid] + sPart[256 + tid] + sPart[512 + tid] + sPart[768 + tid];
            int ll = tid >> 3, d2 = tid & 7;
            if (bid < 64) g_wkr[ll * 512 + colbase + d2] = v;
            else          g_wvr[ll * 512 + colbase + d2] = v;
        }
    }
    gbar();

    // ======== S4: flog + softmax + ep + oacc (block = (l = bid>>2, dq = bid&3))
    {
        float* sF = sm;          // 32
        float* sFa = sm + 32;    // 32
        float* sE = sm + 64;     // 512
        float* sP = sm + 576;    // 1024
        int l = bid >> 2, dq = bid & 3;
        const float* qr = g_rawq + l * P_;
        {
            const float* kr = g_wkr + w * P_;
            float a = 0.f;
#pragma unroll
            for (int i = 0; i < 16; i++) {
                int e = lane + 32 * i;
                a = fmaf(qr[e] + bq[e], kr[e] + bk[e], a);
            }
            a = warp_sum(a);
            if (lane == 0) sF[w] = SCALE_ * a;
        }
        __syncthreads();
        if (w == 0) {
            float x = sF[lane];
            float m = warp_max(x);
            float e = expf(x - m);
            float s = warp_sum(e);
            float f = e / s;
            sFa[lane] = f;
            if (dq == 0) out[OFF_FA + l * 32 + lane] = f;
        }
        __syncthreads();
        if (tid < 512) {
            float a = bv[tid];
#pragma unroll
            for (int j = 0; j < 32; j++) a = fmaf(sFa[j], g_wvr[j * P_ + tid], a);
            sE[tid] = a;
        }
        __syncthreads();
        {
            int dd = tid & 127, ks = tid >> 7;  // ks 0..7
            int d = dq * 128 + dd;
            const float* wcol = Wo + (size_t)(ks * 64) * D_ + d;
            const float* er = sE + ks * 64;
            float a0 = 0.f, a1 = 0.f;
#pragma unroll 8
            for (int k = 0; k < 64; k += 2) {
                a0 = fmaf(er[k], wcol[(size_t)k * D_], a0);
                a1 = fmaf(er[k + 1], wcol[(size_t)(k + 1) * D_], a1);
            }
            sP[ks * 128 + dd] = a0 + a1;
        }
        __syncthreads();
        if (tid < 128) {
            float v = 0.f;
#pragma unroll
            for (int g2 = 0; g2 < 8; g2++) v += sP[g2 * 128 + tid];
            g_oacc[l * 512 + dq * 128 + tid] = v;
        }
    }
    gbar();

    // ======== S5: LN1 (redundant, warp-per-row) + h1 strip GEMM (all blocks)
    {
        float* sEvo = sm;             // 32 x 513
        float* sPart = sm + 16416;    // 1024
        {
            int row = w;
            float x[16];
            float s = 0.f;
#pragma unroll
            for (int i = 0; i < 16; i++) {
                int e = lane + 32 * i;
                x[i] = g_wc[row * 512 + e] + g_oacc[row * 512 + e] + bo[e];
                s += x[i];
            }
            float mean = warp_sum(s) * (1.f / D_);
            float v = 0.f;
#pragma unroll
            for (int i = 0; i < 16; i++) { float d = x[i] - mean; v = fmaf(d, d, v); }
            float inv = rsqrtf(warp_sum(v) * (1.f / D_) + LN_EPS);
#pragma unroll
            for (int i = 0; i < 16; i++) {
                int e = lane + 32 * i;
                float y = (x[i] - mean) * inv * gin[e] + bin[e];
                sEvo[row * 513 + e] = y;
                if (bid == 0) g_evolved[row * 512 + e] = y;
            }
        }
        __syncthreads();
        {
            int dd = w & 15, kh = w >> 4;
            int p = bid * 16 + dd;
            const float* xr = sEvo + lane * 513 + kh * 256;
            const float* wcol = Wa1 + (size_t)(kh * 256) * H_ + p;
            float a0 = 0.f, a1 = 0.f;
#pragma unroll 8
            for (int k = 0; k < 256; k += 2) {
                a0 = fmaf(xr[k], wcol[(size_t)k * H_], a0);
                a1 = fmaf(xr[k + 1], wcol[(size_t)(k + 1) * H_], a1);
            }
            sPart[kh * 512 + lane * 16 + dd] = a0 + a1;
        }
        __syncthreads();
        if (tid < 512) {
            int l = tid >> 4, dd = tid & 15;
            g_h1[l * H_ + bid * 16 + dd] = sPart[tid] + sPart[512 + tid];
        }
    }
    gbar();

    // ======== S6: mlp strip GEMM (block = (ks = bid&3, dseg = bid>>2))
    {
        float* sH = sm;               // 32 x 513
        float* sPart = sm + 16416;    // 1024
        int ks = bid & 3, dseg = bid >> 2;
        for (int i = tid; i < 16384; i += NT) {
            int row = i >> 9, k = i & 511;
            int kg = ks * 512 + k;
            sH[row * 513 + k] = fmaxf(g_h1[row * H_ + kg] + ba1[kg], 0.f);
        }
        __syncthreads();
        {
            int dd = w & 15, kh = w >> 4;
            int d = dseg * 16 + dd;
            const float* hr = sH + lane * 513 + kh * 256;
            const float* wcol = Wa2 + (size_t)(ks * 512 + kh * 256) * D_ + d;
            float a0 = 0.f, a1 = 0.f;
#pragma unroll 8
            for (int k = 0; k < 256; k += 2) {
                a0 = fmaf(hr[k], wcol[(size_t)k * D_], a0);
                a1 = fmaf(hr[k + 1], wcol[(size_t)(k + 1) * D_], a1);
            }
            sPart[kh * 512 + lane * 16 + dd] = a0 + a1;
        }
        __syncthreads();
        if (tid < 512) {
            int l = tid >> 4, dd = tid & 15;
            g_mlpp[ks * 16384 + l * 512 + dseg * 16 + dd] = sPart[tid] + sPart[512 + tid];
        }
    }
    gbar();

    // ======== S7: LN2 (redundant, warp-per-row) + broadcast (all blocks)
    {
        float* sAl = sm;   // 16384
        {
            int row = w;
            float x[16];
            float s = 0.f;
#pragma unroll
            for (int i = 0; i < 16; i++) {
                int e = lane + 32 * i;
                int o = row * 512 + e;
                x[i] = g_evolved[o] + g_mlpp[o] + g_mlpp[16384 + o] +
                       g_mlpp[32768 + o] + g_mlpp[49152 + o] + ba2[e];
                s += x[i];
            }
            float mean = warp_sum(s) * (1.f / D_);
            float v = 0.f;
#pragma unroll
            for (int i = 0; i < 16; i++) { float d = x[i] - mean; v = fmaf(d, d, v); }
            float inv = rsqrtf(warp_sum(v) * (1.f / D_) + LN_EPS);
#pragma unroll
            for (int i = 0; i < 16; i++) {
                int e = lane + 32 * i;
                float y = (x[i] - mean) * inv * gout[e] + bout[e];
                sAl[row * 512 + e] = y;
                if (bid == 0) out[OFF_ALIGNED + row * 512 + e] = y;
            }
        }
        __syncthreads();
        {
            const float4 v = reinterpret_cast<const float4*>(sAl)[gtid & 4095];
            float4* dst = reinterpret_cast<float4*>(out + OFF_AP);
#pragma unroll 8
            for (int k2 = 0; k2 < 32; k2++) __stcs(dst + gtid + k2 * NTH, v);
        }
    }
}

// ---------------- launch ----------------
extern "C" void kernel_launch(void* const* d_in, const int* in_sizes, int n_in,
                              void* d_out, int out_size) {
    (void)in_sizes; (void)n_in; (void)out_size;
    const float* base = (const float*)d_in[0];
    const float* np_  = (const float*)d_in[1];
    const float* te   = (const float*)d_in[2];
    const float* Wt   = (const float*)d_in[3];
    const float* bt   = (const float*)d_in[4];
    const float* Wq   = (const float*)d_in[5];
    const float* bq   = (const float*)d_in[6];
    const float* Wk   = (const float*)d_in[7];
    const float* bk   = (const float*)d_in[8];
    const float* Wv   = (const float*)d_in[9];
    const float* bv   = (const float*)d_in[10];
    const float* Wo   = (const float*)d_in[11];
    const float* bo   = (const float*)d_in[12];
    const float* Wa1  = (const float*)d_in[13];
    const float* ba1  = (const float*)d_in[14];
    const float* Wa2  = (const float*)d_in[15];
    const float* ba2  = (const float*)d_in[16];
    const float* gin  = (const float*)d_in[17];
    const float* bin  = (const float*)d_in[18];
    const float* gout = (const float*)d_in[19];
    const float* bout = (const float*)d_in[20];
    float* out = (float*)d_out;

    static int attr_done = 0;
    if (!attr_done) {
        cudaFuncSetAttribute(mega, cudaFuncAttributeMaxDynamicSharedMemorySize, SMEM_BYTES);
        attr_done = 1;
    }
    mega<<<NB, NT, SMEM_BYTES>>>(base, np_, te, Wt, bt, Wq, bq, Wk, bk, Wv, bv,
                                 Wo, bo, Wa1, ba1, Wa2, ba2, gin, bin, gout, bout, out);
}

// round 16
// speedup vs baseline: 1.2446x; 1.0986x over previous
#include <cuda_runtime.h>
#include <math.h>

#define T_ 1024
#define L_ 32
#define D_ 512
#define P_ 512
#define H_ 2048
#define NB 128
#define NT 1024
#define NTH (NB * NT)   // 131072
#define SCALE_ 0.044194173824159216f  // 1/sqrt(512)
#define LN_EPS 1e-5f
#define PAD 516         // row stride for staged 512-wide arrays (16B-aligned, 4-phase LDS.128)
#define SMEM_BYTES 104448

// output layout offsets (floats)
#define OFF_ALIGNED 0
#define OFF_AP      16384
#define OFF_TW      16793600
#define OFF_FA      16794624

// ---------------- scratch (device globals) ----------------
__device__ __align__(16) float g_bm[T_ * D_];       // base row-sums over L (NOT /32)
__device__ __align__(16) float g_rawq[L_ * P_];     // new_prompt @ Wq (no bias)
__device__ __align__(16) float g_tv[P_];            // task_vec
__device__ __align__(16) float g_pq[P_];            // pooled_q (with bias)
__device__ __align__(16) float g_u[D_];             // Wk @ task_vec
__device__ __align__(16) float g_v[D_];             // Wk @ pooled_q
__device__ __align__(16) float g_c01[2];            // c0 = bk·tv, c1 = bk·pq
__device__ __align__(16) float g_dotu[T_];
__device__ __align__(16) float g_dotv[T_];
__device__ __align__(16) float g_wcp[4 * L_ * D_];  // wc partials (4-way t)
__device__ __align__(16) float g_wc[L_ * D_];       // weighted conditioned
__device__ __align__(16) float g_wkr[L_ * P_];      // wc @ Wk (raw)
__device__ __align__(16) float g_wvr[L_ * P_];      // wc @ Wv (raw)
__device__ __align__(16) float g_oacc[L_ * D_];     // (ep+bv) @ Wo
__device__ __align__(16) float g_evolved[L_ * D_];
__device__ __align__(16) float g_h1[L_ * H_];       // evolved @ Wa1 (raw)
__device__ __align__(16) float g_mlpp[4 * L_ * D_]; // mlp partials (4-way k)

// grid barrier state
__device__ unsigned g_cnt;
__device__ unsigned g_gen;
// sub-group barrier (blocks 116..127)
__device__ unsigned g_cnt2;
__device__ unsigned g_gen2;

// ---------------- grid barrier: single-thread fence ----------------
__device__ __forceinline__ void gbar() {
    __syncthreads();
    if (threadIdx.x == 0) {
        asm volatile("fence.acq_rel.gpu;" ::: "memory");
        unsigned gen = *(volatile unsigned*)&g_gen;
        if (atomicAdd(&g_cnt, 1u) == (unsigned)(NB - 1)) {
            g_cnt = 0u;
            asm volatile("fence.acq_rel.gpu;" ::: "memory");
            *(volatile unsigned*)&g_gen = gen + 1u;
        } else {
            while (*(volatile unsigned*)&g_gen == gen) __nanosleep(32);
            asm volatile("fence.acq_rel.gpu;" ::: "memory");
        }
    }
    __syncthreads();
}

// 12-block sub-barrier (only blocks 116..127 call this)
__device__ __forceinline__ void sub_gbar() {
    __syncthreads();
    if (threadIdx.x == 0) {
        asm volatile("fence.acq_rel.gpu;" ::: "memory");
        unsigned gen = *(volatile unsigned*)&g_gen2;
        if (atomicAdd(&g_cnt2, 1u) == 11u) {
            g_cnt2 = 0u;
            asm volatile("fence.acq_rel.gpu;" ::: "memory");
            *(volatile unsigned*)&g_gen2 = gen + 1u;
        } else {
            while (*(volatile unsigned*)&g_gen2 == gen) __nanosleep(32);
            asm volatile("fence.acq_rel.gpu;" ::: "memory");
        }
    }
    __syncthreads();
}

// ---------------- reductions ----------------
__device__ __forceinline__ float warp_sum(float v) {
#pragma unroll
    for (int o = 16; o > 0; o >>= 1) v += __shfl_xor_sync(0xffffffffu, v, o);
    return v;
}
__device__ __forceinline__ float warp_max(float v) {
#pragma unroll
    for (int o = 16; o > 0; o >>= 1) v = fmaxf(v, __shfl_xor_sync(0xffffffffu, v, o));
    return v;
}
__device__ __forceinline__ float blk_sum(float v, float* red) {
    int w = threadIdx.x >> 5, lane = threadIdx.x & 31;
    v = warp_sum(v);
    if (lane == 0) red[w] = v;
    __syncthreads();
    if (w == 0) {
        float r = red[lane];
        r = warp_sum(r);
        if (lane == 0) red[0] = r;
    }
    __syncthreads();
    float out = red[0];
    __syncthreads();
    return out;
}
__device__ __forceinline__ float blk_max(float v, float* red) {
    int w = threadIdx.x >> 5, lane = threadIdx.x & 31;
    v = warp_max(v);
    if (lane == 0) red[w] = v;
    __syncthreads();
    if (w == 0) {
        float r = red[lane];
        r = warp_max(r);
        if (lane == 0) red[0] = r;
    }
    __syncthreads();
    float out = red[0];
    __syncthreads();
    return out;
}
__device__ __forceinline__ float dot4(float4 a, float4 b) {
    return fmaf(a.x, b.x, fmaf(a.y, b.y, fmaf(a.z, b.z, a.w * b.w)));
}
__device__ __forceinline__ void l2_prefetch(const void* p) {
    asm volatile("prefetch.global.L2 [%0];" :: "l"(p));
}

// ---------------- megakernel ----------------
__global__ void __launch_bounds__(NT, 1)
mega(const float* __restrict__ base, const float* __restrict__ np_,
     const float* __restrict__ te, const float* __restrict__ Wt,
     const float* __restrict__ bt, const float* __restrict__ Wq,
     const float* __restrict__ bq, const float* __restrict__ Wk,
     const float* __restrict__ bk, const float* __restrict__ Wv,
     const float* __restrict__ bv, const float* __restrict__ Wo,
     const float* __restrict__ bo, const float* __restrict__ Wa1,
     const float* __restrict__ ba1, const float* __restrict__ Wa2,
     const float* __restrict__ ba2, const float* __restrict__ gin,
     const float* __restrict__ bin, const float* __restrict__ gout,
     const float* __restrict__ bout, float* __restrict__ out) {
    extern __shared__ float sm[];

    const int bid = blockIdx.x;
    const int tid = threadIdx.x;
    const int gtid = bid * NT + tid;
    const int w = tid >> 5, lane = tid & 31;
    const float4* base4 = reinterpret_cast<const float4*>(base);

    // ======== S0 (one global stage, three concurrent roles):
    //   blk 0-7:    rawq reuse-GEMM
    //   blk 8-115:  L2-prefetch weights + base row-sums (THE DRAM pass)
    //   blk 116-127: tv/pq -> sub-barrier -> u,v + c0,c1 (hidden under stream)
    if (bid < 8) {
        float* npS = sm;           // 8 x 512
        float* sPart = sm + 4096;  // 4 x 2048
        int lq = bid >> 1, ph = bid & 1;
        for (int i = tid; i < 4096; i += NT) {
            int l = i >> 9, k = i & 511;
            npS[i] = np_[(lq * 8 + l) * 512 + k];
        }
        __syncthreads();
        int poff = tid & 255, sub = tid >> 8;   // 4-way k-split of 512
        const float* wq = Wq + (size_t)(sub * 128) * P_ + ph * 256 + poff;
        float acc[8] = {0.f, 0.f, 0.f, 0.f, 0.f, 0.f, 0.f, 0.f};
        const float* nr = npS + sub * 128;
#pragma unroll 4
        for (int kk = 0; kk < 128; kk++) {
            float wv = wq[(size_t)kk * P_];
#pragma unroll
            for (int l = 0; l < 8; l++) acc[l] = fmaf(nr[l * 512 + kk], wv, acc[l]);
        }
#pragma unroll
        for (int l = 0; l < 8; l++) sPart[sub * 2048 + poff * 8 + l] = acc[l];
        __syncthreads();
        for (int m = tid; m < 2048; m += NT) {
            float val = sPart[m] + sPart[2048 + m] + sPart[4096 + m] + sPart[6144 + m];
            int l = m & 7, po = m >> 3;
            g_rawq[(lq * 8 + l) * 512 + ph * 256 + po] = val;
        }
    } else if (bid < 116) {
        {
            int j = (bid - 8) * NT + tid;   // 128B line id
            if (j < 32768) l2_prefetch((const char*)Wa1 + (size_t)j * 128);
            else if (j < 65536) l2_prefetch((const char*)Wa2 + (size_t)(j - 32768) * 128);
            else if (j < 73728) l2_prefetch((const char*)Wo + (size_t)(j - 65536) * 128);
            else if (j < 81920) l2_prefetch((const char*)Wk + (size_t)(j - 73728) * 128);
            else if (j < 90112) l2_prefetch((const char*)Wv + (size_t)(j - 81920) * 128);
        }
        for (int i = (bid - 8) * NT + tid; i < 131072; i += 108 * NT) {
            int t = i >> 7, c = i & 127;
            const float4* p = base4 + (size_t)t * 4096 + c;
            float4 s = {0.f, 0.f, 0.f, 0.f};
#pragma unroll 8
            for (int l = 0; l < L_; l++) {
                float4 b4 = p[l * 128];
                s.x += b4.x; s.y += b4.y; s.z += b4.z; s.w += b4.w;
            }
            reinterpret_cast<float4*>(g_bm)[i] = s;
        }
    } else {
        if (bid < 118) {
            float* teS = sm;           // 512
            float* sPart = sm + 512;   // 1024
            int q = bid - 116;
            if (tid < 512) teS[tid] = te[tid];
            __syncthreads();
            int poff = tid & 255, sub = tid >> 8;
            int p = q * 256 + poff;
            const float* wcol = Wt + (size_t)(sub * 128) * P_ + p;
            const float* tr = teS + sub * 128;
            float a = 0.f;
#pragma unroll 8
            for (int kk = 0; kk < 128; kk++) a = fmaf(tr[kk], wcol[(size_t)kk * P_], a);
            sPart[sub * 256 + poff] = a;
            __syncthreads();
            if (tid < 256) {
                int p2 = q * 256 + tid;
                float v = sPart[tid] + sPart[256 + tid] + sPart[512 + tid] + sPart[768 + tid];
                g_tv[p2] = tanhf(v + bt[p2]);
            }
        } else if (bid < 120) {
            float* nmS = sm;           // 512
            float* sPart = sm + 512;   // 1024
            int q = bid - 118;
            if (tid < 512) {
                float s = 0.f;
#pragma unroll 8
                for (int l = 0; l < 32; l++) s += np_[l * 512 + tid];
                nmS[tid] = s * (1.f / 32.f);
            }
            __syncthreads();
            int poff = tid & 255, sub = tid >> 8;
            int p = q * 256 + poff;
            const float* wcol = Wq + (size_t)(sub * 128) * P_ + p;
            const float* nr = nmS + sub * 128;
            float a = 0.f;
#pragma unroll 8
            for (int kk = 0; kk < 128; kk++) a = fmaf(nr[kk], wcol[(size_t)kk * P_], a);
            sPart[sub * 256 + poff] = a;
            __syncthreads();
            if (tid < 256) {
                int p2 = q * 256 + tid;
                float v = sPart[tid] + sPart[256 + tid] + sPart[512 + tid] + sPart[768 + tid];
                g_pq[p2] = v + bq[p2];
            }
        }
        sub_gbar();
        {
            float* sTV = sm;          // 512
            float* sPQ = sm + 512;    // 512
            float* sRed = sm + 1024;  // 32
            if (tid < 512) sTV[tid] = g_tv[tid];
            else if (tid < 1024) sPQ[tid - 512] = g_pq[tid - 512];
            __syncthreads();
            const float4* tv4 = reinterpret_cast<const float4*>(sTV);
            const float4* pq4 = reinterpret_cast<const float4*>(sPQ);
            for (int tk = (bid - 116) * 32 + w; tk < 1024; tk += 384) {
                int sel = tk >> 9, d = tk & 511;
                const float4* row = reinterpret_cast<const float4*>(Wk + (size_t)d * P_);
                const float4* xv = sel ? pq4 : tv4;
                float a = 0.f;
#pragma unroll
                for (int i = 0; i < 4; i++) a += dot4(row[lane + 32 * i], xv[lane + 32 * i]);
                a = warp_sum(a);
                if (lane == 0) { if (sel) g_v[d] = a; else g_u[d] = a; }
            }
            if (bid == 127) {
                float t0 = (tid < 512) ? bk[tid] * sTV[tid] : 0.f;
                float c0 = blk_sum(t0, sRed);
                float t1 = (tid < 512) ? bk[tid] * sPQ[tid] : 0.f;
                float c1 = blk_sum(t1, sRed);
                if (tid == 0) { g_c01[0] = c0; g_c01[1] = c1; }
            }
        }
    }
    gbar();

    // ======== S1: dots from g_bm (all blocks; tiny 2MB pass; fold 1/32 here)
    {
        float4* sU4 = reinterpret_cast<float4*>(sm);         // 128
        float4* sV4 = reinterpret_cast<float4*>(sm) + 128;   // 128
        float* sPu = sm + 1024;  // 32
        float* sPv = sm + 1056;  // 32
        if (tid < 128) sU4[tid] = reinterpret_cast<const float4*>(g_u)[tid];
        else if (tid < 256) sV4[tid - 128] = reinterpret_cast<const float4*>(g_v)[tid - 128];
        __syncthreads();
        int t = bid * 8 + (w >> 2);
        int seg = w & 3;
        float4 b4 = reinterpret_cast<const float4*>(g_bm)[t * 128 + seg * 32 + lane];
        float au = dot4(b4, sU4[seg * 32 + lane]);
        float av = dot4(b4, sV4[seg * 32 + lane]);
        au = warp_sum(au);
        av = warp_sum(av);
        if (lane == 0) { sPu[w] = au; sPv[w] = av; }
        __syncthreads();
        if (tid < 8) {
            float su = sPu[4 * tid] + sPu[4 * tid + 1] + sPu[4 * tid + 2] + sPu[4 * tid + 3];
            g_dotu[bid * 8 + tid] = su * (1.f / 32.f);
        } else if (tid < 16) {
            int q = tid - 8;
            float sv = sPv[4 * q] + sPv[4 * q + 1] + sPv[4 * q + 2] + sPv[4 * q + 3];
            g_dotv[bid * 8 + q] = sv * (1.f / 32.f);
        }
    }
    gbar();

    // ======== S2: task softmaxes (redundant; tid==t) + wc partials (base from L2)
    {
        float* sC = sm;                // 1024 coef
        float* sRed = sm + 1024;       // 32
        float4* sP4 = reinterpret_cast<float4*>(sm + 1056); // 1024 float4

        float c0 = g_c01[0], c1 = g_c01[1];

        float s1 = SCALE_ * (g_dotu[tid] + c0);
        float dv = g_dotv[tid];
        float m1 = blk_max(s1, sRed);
        float e1 = expf(s1 - m1);
        float tw1 = e1 / blk_sum(e1, sRed);

        float s2 = SCALE_ * ((1.f + tw1) * dv + c1);
        float m2 = blk_max(s2, sRed);
        float e2 = expf(s2 - m2);
        float ta = e2 / blk_sum(e2, sRed);

        float tw = 0.5f * (tw1 + ta);
        float S = blk_sum(tw, sRed);
        float tw2 = tw / fmaxf(S, 1e-6f);
        sC[tid] = tw2 * (1.f + tw1);
        if (bid == 0) out[OFF_TW + tid] = tw2;
        __syncthreads();

        int l = bid >> 2, q = bid & 3;
        int c = tid & 127, ts = tid >> 7;       // ts 0..7
        int t0 = q * 256 + ts * 32;
        const float4* bp = base4 + (size_t)t0 * 4096 + l * 128 + c;
        const float* cf = sC + t0;
        float4 acc = {0.f, 0.f, 0.f, 0.f};
#pragma unroll 8
        for (int i = 0; i < 32; i++) {
            float cv = cf[i];
            float4 b4 = bp[i * 4096];
            acc.x = fmaf(cv, b4.x, acc.x);
            acc.y = fmaf(cv, b4.y, acc.y);
            acc.z = fmaf(cv, b4.z, acc.z);
            acc.w = fmaf(cv, b4.w, acc.w);
        }
        sP4[ts * 128 + c] = acc;
        __syncthreads();
        if (tid < 128) {
            float4 a = sP4[tid];
#pragma unroll
            for (int g2 = 1; g2 < 8; g2++) {
                float4 b = sP4[g2 * 128 + tid];
                a.x += b.x; a.y += b.y; a.z += b.z; a.w += b.w;
            }
            reinterpret_cast<float4*>(g_wcp)[q * 4096 + l * 128 + tid] = a;
        }
    }
    gbar();

    // ======== S3: fold wc + wkr/wvr strip GEMM, weights STAGED in smem
    {
        float* sX = sm;               // 32 x PAD
        float* sW = sm + 32 * PAD;    // 8 x PAD (transposed strip [dd][k])
        float* sPart = sW + 8 * PAD;  // 1024
        const float* W = (bid < 64) ? Wk : Wv;
        int colbase = (bid & 63) * 8;
        {   // stage 8-col weight strip: 1024 float4, 1/thread
            int k = tid >> 1, c4 = tid & 1;
            float4 v = *reinterpret_cast<const float4*>(W + (size_t)k * P_ + colbase + c4 * 4);
            sW[(c4 * 4 + 0) * PAD + k] = v.x;
            sW[(c4 * 4 + 1) * PAD + k] = v.y;
            sW[(c4 * 4 + 2) * PAD + k] = v.z;
            sW[(c4 * 4 + 3) * PAD + k] = v.w;
        }
        for (int i = tid; i < 16384; i += NT) {
            float x = g_wcp[i] + g_wcp[16384 + i] + g_wcp[32768 + i] + g_wcp[49152 + i];
            int l = i >> 9, k = i & 511;
            sX[l * PAD + k] = x;
            if (bid == 0) g_wc[i] = x;
        }
        __syncthreads();
        {   // warp = (dd = w&7, kh = w>>3); lane = l
            int dd = w & 7, kh = w >> 3;
            const float4* xr4 = reinterpret_cast<const float4*>(sX + lane * PAD + kh * 128);
            const float4* w4 = reinterpret_cast<const float4*>(sW + dd * PAD + kh * 128);
            float a0 = 0.f, a1 = 0.f;
#pragma unroll
            for (int k4 = 0; k4 < 32; k4 += 2) {
                a0 += dot4(xr4[k4], w4[k4]);
                a1 += dot4(xr4[k4 + 1], w4[k4 + 1]);
            }
            sPart[kh * 256 + lane * 8 + dd] = a0 + a1;
        }
        __syncthreads();
        if (tid < 256) {
            float v = sPart[tid] + sPart[256 + tid] + sPart[512 + tid] + sPart[768 + tid];
            int ll = tid >> 3, d2 = tid & 7;
            if (bid < 64) g_wkr[ll * 512 + colbase + d2] = v;
            else          g_wvr[ll * 512 + colbase + d2] = v;
        }
    }
    gbar();

    // ======== S4: flog + softmax + ep + oacc (block = (l = bid>>2, dq = bid&3))
    {
        float* sF = sm;          // 32
        float* sFa = sm + 32;    // 32
        float* sE = sm + 64;     // 512
        float* sP = sm + 576;    // 1024
        int l = bid >> 2, dq = bid & 3;
        const float* qr = g_rawq + l * P_;
        {
            const float* kr = g_wkr + w * P_;
            float a = 0.f;
#pragma unroll
            for (int i = 0; i < 16; i++) {
                int e = lane + 32 * i;
                a = fmaf(qr[e] + bq[e], kr[e] + bk[e], a);
            }
            a = warp_sum(a);
            if (lane == 0) sF[w] = SCALE_ * a;
        }
        __syncthreads();
        if (w == 0) {
            float x = sF[lane];
            float m = warp_max(x);
            float e = expf(x - m);
            float s = warp_sum(e);
            float f = e / s;
            sFa[lane] = f;
            if (dq == 0) out[OFF_FA + l * 32 + lane] = f;
        }
        __syncthreads();
        if (tid < 512) {
            float a = bv[tid];
#pragma unroll
            for (int j = 0; j < 32; j++) a = fmaf(sFa[j], g_wvr[j * P_ + tid], a);
            sE[tid] = a;
        }
        __syncthreads();
        {
            int dd = tid & 127, ks = tid >> 7;  // ks 0..7
            int d = dq * 128 + dd;
            const float* wcol = Wo + (size_t)(ks * 64) * D_ + d;
            const float* er = sE + ks * 64;
            float a0 = 0.f, a1 = 0.f;
#pragma unroll 8
            for (int k = 0; k < 64; k += 2) {
                a0 = fmaf(er[k], wcol[(size_t)k * D_], a0);
                a1 = fmaf(er[k + 1], wcol[(size_t)(k + 1) * D_], a1);
            }
            sP[ks * 128 + dd] = a0 + a1;
        }
        __syncthreads();
        if (tid < 128) {
            float v = 0.f;
#pragma unroll
            for (int g2 = 0; g2 < 8; g2++) v += sP[g2 * 128 + tid];
            g_oacc[l * 512 + dq * 128 + tid] = v;
        }
    }
    gbar();

    // ======== S5: LN1 + h1 strip GEMM, Wa1 strip STAGED in smem
    {
        float* sEvo = sm;              // 32 x PAD
        float* sW = sm + 32 * PAD;     // 16 x PAD (transposed [dd][k])
        float* sPart = sW + 16 * PAD;  // 1024
        {   // stage Wa1 strip (cols bid*16..+16): 2048 float4, 2/thread
#pragma unroll
            for (int ii = 0; ii < 2; ii++) {
                int idx = ii * NT + tid;          // 0..2047
                int k = idx >> 2, c4 = idx & 3;
                float4 v = *reinterpret_cast<const float4*>(
                    Wa1 + (size_t)k * H_ + bid * 16 + c4 * 4);
                sW[(c4 * 4 + 0) * PAD + k] = v.x;
                sW[(c4 * 4 + 1) * PAD + k] = v.y;
                sW[(c4 * 4 + 2) * PAD + k] = v.z;
                sW[(c4 * 4 + 3) * PAD + k] = v.w;
            }
        }
        {   // LN1 (warp-per-row redundant)
            int row = w;
            float x[16];
            float s = 0.f;
#pragma unroll
            for (int i = 0; i < 16; i++) {
                int e = lane + 32 * i;
                x[i] = g_wc[row * 512 + e] + g_oacc[row * 512 + e] + bo[e];
                s += x[i];
            }
            float mean = warp_sum(s) * (1.f / D_);
            float v = 0.f;
#pragma unroll
            for (int i = 0; i < 16; i++) { float d = x[i] - mean; v = fmaf(d, d, v); }
            float inv = rsqrtf(warp_sum(v) * (1.f / D_) + LN_EPS);
#pragma unroll
            for (int i = 0; i < 16; i++) {
                int e = lane + 32 * i;
                float y = (x[i] - mean) * inv * gin[e] + bin[e];
                sEvo[row * PAD + e] = y;
                if (bid == 0) g_evolved[row * 512 + e] = y;
            }
        }
        __syncthreads();
        {   // warp = (dd = w&15, kh = w>>4); lane = row
            int dd = w & 15, kh = w >> 4;
            const float4* xr4 = reinterpret_cast<const float4*>(sEvo + lane * PAD + kh * 256);
            const float4* w4 = reinterpret_cast<const float4*>(sW + dd * PAD + kh * 256);
            float a0 = 0.f, a1 = 0.f;
#pragma unroll
            for (int k4 = 0; k4 < 64; k4 += 2) {
                a0 += dot4(xr4[k4], w4[k4]);
                a1 += dot4(xr4[k4 + 1], w4[k4 + 1]);
            }
            sPart[kh * 512 + lane * 16 + dd] = a0 + a1;
        }
        __syncthreads();
        if (tid < 512) {
            int l = tid >> 4, dd = tid & 15;
            g_h1[l * H_ + bid * 16 + dd] = sPart[tid] + sPart[512 + tid];
        }
    }
    gbar();

    // ======== S6: mlp strip GEMM (ks = bid&3, dseg = bid>>2), Wa2 strip STAGED
    {
        float* sH = sm;                // 32 x PAD
        float* sW = sm + 32 * PAD;     // 16 x PAD (transposed [dd][k])
        float* sPart = sW + 16 * PAD;  // 1024
        int ks = bid & 3, dseg = bid >> 2;
        {   // stage Wa2 strip: rows kg = ks*512..+512, cols dseg*16..+16
#pragma unroll
            for (int ii = 0; ii < 2; ii++) {
                int idx = ii * NT + tid;
                int k = idx >> 2, c4 = idx & 3;
                float4 v = *reinterpret_cast<const float4*>(
                    Wa2 + (size_t)(ks * 512 + k) * D_ + dseg * 16 + c4 * 4);
                sW[(c4 * 4 + 0) * PAD + k] = v.x;
                sW[(c4 * 4 + 1) * PAD + k] = v.y;
                sW[(c4 * 4 + 2) * PAD + k] = v.z;
                sW[(c4 * 4 + 3) * PAD + k] = v.w;
            }
        }
        for (int i = tid; i < 16384; i += NT) {
            int row = i >> 9, k = i & 511;
            int kg = ks * 512 + k;
            sH[row * PAD + k] = fmaxf(g_h1[row * H_ + kg] + ba1[kg], 0.f);
        }
        __syncthreads();
        {
            int dd = w & 15, kh = w >> 4;
            const float4* hr4 = reinterpret_cast<const float4*>(sH + lane * PAD + kh * 256);
            const float4* w4 = reinterpret_cast<const float4*>(sW + dd * PAD + kh * 256);
            float a0 = 0.f, a1 = 0.f;
#pragma unroll
            for (int k4 = 0; k4 < 64; k4 += 2) {
                a0 += dot4(hr4[k4], w4[k4]);
                a1 += dot4(hr4[k4 + 1], w4[k4 + 1]);
            }
            sPart[kh * 512 + lane * 16 + dd] = a0 + a1;
        }
        __syncthreads();
        if (tid < 512) {
            int l = tid >> 4, dd = tid & 15;
            g_mlpp[ks * 16384 + l * 512 + dseg * 16 + dd] = sPart[tid] + sPart[512 + tid];
        }
    }
    gbar();

    // ======== S7: LN2 (redundant, warp-per-row) + broadcast (all blocks)
    {
        float* sAl = sm;   // 16384
        {
            int row = w;
            float x[16];
            float s = 0.f;
#pragma unroll
            for (int i = 0; i < 16; i++) {
                int e = lane + 32 * i;
                int o = row * 512 + e;
                x[i] = g_evolved[o] + g_mlpp[o] + g_mlpp[16384 + o] +
                       g_mlpp[32768 + o] + g_mlpp[49152 + o] + ba2[e];
                s += x[i];
            }
            float mean = warp_sum(s) * (1.f / D_);
            float v = 0.f;
#pragma unroll
            for (int i = 0; i < 16; i++) { float d = x[i] - mean; v = fmaf(d, d, v); }
            float inv = rsqrtf(warp_sum(v) * (1.f / D_) + LN_EPS);
#pragma unroll
            for (int i = 0; i < 16; i++) {
                int e = lane + 32 * i;
                float y = (x[i] - mean) * inv * gout[e] + bout[e];
                sAl[row * 512 + e] = y;
                if (bid == 0) out[OFF_ALIGNED + row * 512 + e] = y;
            }
        }
        __syncthreads();
        {
            const float4 v = reinterpret_cast<const float4*>(sAl)[gtid & 4095];
            float4* dst = reinterpret_cast<float4*>(out + OFF_AP);
#pragma unroll 8
            for (int k2 = 0; k2 < 32; k2++) __stcs(dst + gtid + k2 * NTH, v);
        }
    }
}

// ---------------- launch ----------------
extern "C" void kernel_launch(void* const* d_in, const int* in_sizes, int n_in,
                              void* d_out, int out_size) {
    (void)in_sizes; (void)n_in; (void)out_size;
    const float* base = (const float*)d_in[0];
    const float* np_  = (const float*)d_in[1];
    const float* te   = (const float*)d_in[2];
    const float* Wt   = (const float*)d_in[3];
    const float* bt   = (const float*)d_in[4];
    const float* Wq   = (const float*)d_in[5];
    const float* bq   = (const float*)d_in[6];
    const float* Wk   = (const float*)d_in[7];
    const float* bk   = (const float*)d_in[8];
    const float* Wv   = (const float*)d_in[9];
    const float* bv   = (const float*)d_in[10];
    const float* Wo   = (const float*)d_in[11];
    const float* bo   = (const float*)d_in[12];
    const float* Wa1  = (const float*)d_in[13];
    const float* ba1  = (const float*)d_in[14];
    const float* Wa2  = (const float*)d_in[15];
    const float* ba2  = (const float*)d_in[16];
    const float* gin  = (const float*)d_in[17];
    const float* bin  = (const float*)d_in[18];
    const float* gout = (const float*)d_in[19];
    const float* bout = (const float*)d_in[20];
    float* out = (float*)d_out;

    static int attr_done = 0;
    if (!attr_done) {
        cudaFuncSetAttribute(mega, cudaFuncAttributeMaxDynamicSharedMemorySize, SMEM_BYTES);
        attr_done = 1;
    }
    mega<<<NB, NT, SMEM_BYTES>>>(base, np_, te, Wt, bt, Wq, bq, Wk, bk, Wv, bv,
                                 Wo, bo, Wa1, ba1, Wa2, ba2, gin, bin, gout, bout, out);
}